// round 2
// baseline (speedup 1.0000x reference)
#include <cuda_runtime.h>

// FlashMoE baseline: fp32 SIMT, sparse expert dispatch.
// Pipeline:
//   1) encoder_gemm: enc = x @ W_enc^T + b  -> g_encoded AND out (out starts as enc)
//   2) zero_counts
//   3) routing_kernel: logits = enc @ Wg^T, top-2, softmax, scatter into per-expert lists
//   4) expert_kernel: per (expert, 128-token tile): S = silu(Xg @ U_e^T) * (w*gamma),
//      delta_tile = S @ V_e^T, atomicAdd into out rows.

#define B_TOK 16384
#define DM    2048
#define NEXP  16
#define RR    128
#define CAP   16384

__device__ float g_encoded[(size_t)B_TOK * DM];
__device__ int   g_cnt[NEXP];
__device__ int   g_tok[NEXP * CAP];
__device__ float g_wgt[NEXP * CAP];

// ---------------------------------------------------------------------------
// Encoder GEMM: C[r,c] = sum_k A[r,k]*W[c,k] + bias[c]; writes g_encoded and out.
// 128x128 block tile, BK=16, 8x8 per thread, 256 threads.
// ---------------------------------------------------------------------------
__global__ __launch_bounds__(256) void encoder_gemm(
    const float* __restrict__ A, const float* __restrict__ W,
    const float* __restrict__ bias, float* __restrict__ out)
{
    __shared__ float As[16][132];
    __shared__ float Bs[16][132];
    const int tid = threadIdx.x;
    const int tx = tid & 15;
    const int ty = tid >> 4;
    const int rowBase = blockIdx.y * 128;
    const int colBase = blockIdx.x * 128;
    const int lrow = tid >> 2;          // 0..63
    const int lk   = (tid & 3) << 2;    // 0,4,8,12

    const float* a0 = A + (size_t)(rowBase + lrow)      * DM + lk;
    const float* a1 = A + (size_t)(rowBase + lrow + 64) * DM + lk;
    const float* w0 = W + (size_t)(colBase + lrow)      * DM + lk;
    const float* w1 = W + (size_t)(colBase + lrow + 64) * DM + lk;

    float acc[8][8];
    #pragma unroll
    for (int i = 0; i < 8; ++i)
        #pragma unroll
        for (int j = 0; j < 8; ++j) acc[i][j] = 0.f;

    for (int kt = 0; kt < DM; kt += 16) {
        float4 av0 = *(const float4*)(a0 + kt);
        float4 av1 = *(const float4*)(a1 + kt);
        float4 bv0 = *(const float4*)(w0 + kt);
        float4 bv1 = *(const float4*)(w1 + kt);
        As[lk+0][lrow] = av0.x; As[lk+1][lrow] = av0.y;
        As[lk+2][lrow] = av0.z; As[lk+3][lrow] = av0.w;
        As[lk+0][lrow+64] = av1.x; As[lk+1][lrow+64] = av1.y;
        As[lk+2][lrow+64] = av1.z; As[lk+3][lrow+64] = av1.w;
        Bs[lk+0][lrow] = bv0.x; Bs[lk+1][lrow] = bv0.y;
        Bs[lk+2][lrow] = bv0.z; Bs[lk+3][lrow] = bv0.w;
        Bs[lk+0][lrow+64] = bv1.x; Bs[lk+1][lrow+64] = bv1.y;
        Bs[lk+2][lrow+64] = bv1.z; Bs[lk+3][lrow+64] = bv1.w;
        __syncthreads();
        #pragma unroll
        for (int k = 0; k < 16; ++k) {
            float ra[8], rb[8];
            *(float4*)&ra[0] = *(const float4*)&As[k][ty*8];
            *(float4*)&ra[4] = *(const float4*)&As[k][ty*8+4];
            *(float4*)&rb[0] = *(const float4*)&Bs[k][tx*8];
            *(float4*)&rb[4] = *(const float4*)&Bs[k][tx*8+4];
            #pragma unroll
            for (int i = 0; i < 8; ++i)
                #pragma unroll
                for (int j = 0; j < 8; ++j)
                    acc[i][j] += ra[i] * rb[j];
        }
        __syncthreads();
    }

    float bj[8];
    #pragma unroll
    for (int j = 0; j < 8; ++j) bj[j] = bias[colBase + tx*8 + j];

    #pragma unroll
    for (int i = 0; i < 8; ++i) {
        size_t off = (size_t)(rowBase + ty*8 + i) * DM + colBase + tx*8;
        float4 v0, v1;
        v0.x = acc[i][0] + bj[0]; v0.y = acc[i][1] + bj[1];
        v0.z = acc[i][2] + bj[2]; v0.w = acc[i][3] + bj[3];
        v1.x = acc[i][4] + bj[4]; v1.y = acc[i][5] + bj[5];
        v1.z = acc[i][6] + bj[6]; v1.w = acc[i][7] + bj[7];
        *(float4*)(g_encoded + off)     = v0;
        *(float4*)(g_encoded + off + 4) = v1;
        *(float4*)(out + off)     = v0;
        *(float4*)(out + off + 4) = v1;
    }
}

// ---------------------------------------------------------------------------
__global__ void zero_counts()
{
    if (threadIdx.x < NEXP) g_cnt[threadIdx.x] = 0;
}

// ---------------------------------------------------------------------------
// Routing: one warp handles 2 tokens. logits = enc @ Wg^T (TAU=1), top-2,
// softmax over the 2 values (matches reference masked softmax), scatter.
// Top-2 of top-4 == top-2 overall; argmax loops with '>' keep lowest index
// on ties, matching jax.lax.top_k stability.
// ---------------------------------------------------------------------------
__global__ __launch_bounds__(256) void routing_kernel(
    const float* __restrict__ Wg)
{
    const int warp = (blockIdx.x * blockDim.x + threadIdx.x) >> 5;
    const int lane = threadIdx.x & 31;
    const int b0 = warp * 2;
    if (b0 >= B_TOK) return;

    const float4* x0 = (const float4*)(g_encoded + (size_t)b0 * DM);
    const float4* x1 = (const float4*)(g_encoded + (size_t)(b0 + 1) * DM);
    const float4* wg = (const float4*)Wg;

    float a0[NEXP], a1[NEXP];
    #pragma unroll
    for (int m = 0; m < NEXP; ++m) { a0[m] = 0.f; a1[m] = 0.f; }

    for (int it = 0; it < DM / 128; ++it) {   // 16 iterations
        int d4 = it * 32 + lane;
        float4 v0 = x0[d4];
        float4 v1 = x1[d4];
        #pragma unroll
        for (int m = 0; m < NEXP; ++m) {
            float4 w = wg[m * (DM / 4) + d4];
            a0[m] += v0.x*w.x + v0.y*w.y + v0.z*w.z + v0.w*w.w;
            a1[m] += v1.x*w.x + v1.y*w.y + v1.z*w.z + v1.w*w.w;
        }
    }
    #pragma unroll
    for (int m = 0; m < NEXP; ++m) {
        #pragma unroll
        for (int off = 16; off > 0; off >>= 1) {
            a0[m] += __shfl_xor_sync(0xffffffffu, a0[m], off);
            a1[m] += __shfl_xor_sync(0xffffffffu, a1[m], off);
        }
    }
    if (lane < 2) {
        float v[NEXP];
        #pragma unroll
        for (int m = 0; m < NEXP; ++m) v[m] = (lane == 0) ? a0[m] : a1[m];
        const int b = b0 + lane;

        float best = v[0]; int bi = 0;
        #pragma unroll
        for (int m = 1; m < NEXP; ++m)
            if (v[m] > best) { best = v[m]; bi = m; }
        float best2 = -3.402823466e38f; int bi2 = 0;
        #pragma unroll
        for (int m = 0; m < NEXP; ++m)
            if (m != bi && v[m] > best2) { best2 = v[m]; bi2 = m; }

        float e2 = __expf(best2 - best);
        float denom = 1.f + e2 + 1e-12f;
        float w1 = 1.f / denom;
        float w2 = e2 / denom;
        if (w1 > 1e-12f) {
            int p = atomicAdd(&g_cnt[bi], 1);
            g_tok[bi * CAP + p] = b; g_wgt[bi * CAP + p] = w1;
        }
        if (w2 > 1e-12f) {
            int p = atomicAdd(&g_cnt[bi2], 1);
            g_tok[bi2 * CAP + p] = b; g_wgt[bi2 * CAP + p] = w2;
        }
    }
}

// ---------------------------------------------------------------------------
// Expert kernel: block = (128-token tile of expert e).
// Phase 1: S[128 tok][128 r] = silu(Xg @ U_e^T) * (w*gamma), stored transposed
//          in smem as Ssh[r][tok].
// Phase 2: for each 128-wide d-tile: acc = S @ Vtile^T, atomicAdd into out.
// ---------------------------------------------------------------------------
#define EXP_SMEM_BYTES ((2*16*132 + 128*132) * 4)

__global__ __launch_bounds__(256) void expert_kernel(
    const float* __restrict__ U, const float* __restrict__ V,
    const float* __restrict__ gamma, float* __restrict__ out)
{
    const int e = blockIdx.y;
    const int n = g_cnt[e];
    const int t0 = blockIdx.x * 128;
    if (t0 >= n) return;

    extern __shared__ float sm[];
    float* As  = sm;                 // [16][132]
    float* Bs  = sm + 16 * 132;      // [16][132]  (reused as Vs in phase 2)
    float* Ssh = sm + 2 * 16 * 132;  // [128][132], Ssh[r][tok]
    __shared__ int   tok_s[128];
    __shared__ float cw_s[128];

    const int tid = threadIdx.x;
    if (tid < 128) {
        int idx = t0 + tid;
        if (idx < n) {
            tok_s[tid] = g_tok[e * CAP + idx];
            cw_s[tid]  = g_wgt[e * CAP + idx] * gamma[e];
        } else {
            tok_s[tid] = 0;
            cw_s[tid]  = 0.f;
        }
    }
    __syncthreads();

    const int tx = tid & 15;
    const int ty = tid >> 4;
    const int lrow = tid >> 2;
    const int lk   = (tid & 3) << 2;

    const float* ar0 = g_encoded + (size_t)tok_s[lrow]      * DM + lk;
    const float* ar1 = g_encoded + (size_t)tok_s[lrow + 64] * DM + lk;
    const float* Ue  = U + (size_t)e * RR * DM;
    const float* u0  = Ue + (size_t)lrow        * DM + lk;
    const float* u1  = Ue + (size_t)(lrow + 64) * DM + lk;

    float acc[8][8];
    #pragma unroll
    for (int i = 0; i < 8; ++i)
        #pragma unroll
        for (int j = 0; j < 8; ++j) acc[i][j] = 0.f;

    // ---- Phase 1: up-projection, K = 2048 ----
    for (int kt = 0; kt < DM; kt += 16) {
        float4 av0 = *(const float4*)(ar0 + kt);
        float4 av1 = *(const float4*)(ar1 + kt);
        float4 bv0 = *(const float4*)(u0 + kt);
        float4 bv1 = *(const float4*)(u1 + kt);
        As[(lk+0)*132 + lrow] = av0.x; As[(lk+1)*132 + lrow] = av0.y;
        As[(lk+2)*132 + lrow] = av0.z; As[(lk+3)*132 + lrow] = av0.w;
        As[(lk+0)*132 + lrow+64] = av1.x; As[(lk+1)*132 + lrow+64] = av1.y;
        As[(lk+2)*132 + lrow+64] = av1.z; As[(lk+3)*132 + lrow+64] = av1.w;
        Bs[(lk+0)*132 + lrow] = bv0.x; Bs[(lk+1)*132 + lrow] = bv0.y;
        Bs[(lk+2)*132 + lrow] = bv0.z; Bs[(lk+3)*132 + lrow] = bv0.w;
        Bs[(lk+0)*132 + lrow+64] = bv1.x; Bs[(lk+1)*132 + lrow+64] = bv1.y;
        Bs[(lk+2)*132 + lrow+64] = bv1.z; Bs[(lk+3)*132 + lrow+64] = bv1.w;
        __syncthreads();
        #pragma unroll
        for (int k = 0; k < 16; ++k) {
            float ra[8], rb[8];
            *(float4*)&ra[0] = *(const float4*)&As[k*132 + ty*8];
            *(float4*)&ra[4] = *(const float4*)&As[k*132 + ty*8 + 4];
            *(float4*)&rb[0] = *(const float4*)&Bs[k*132 + tx*8];
            *(float4*)&rb[4] = *(const float4*)&Bs[k*132 + tx*8 + 4];
            #pragma unroll
            for (int i = 0; i < 8; ++i)
                #pragma unroll
                for (int j = 0; j < 8; ++j)
                    acc[i][j] += ra[i] * rb[j];
        }
        __syncthreads();
    }

    // silu * (w*gamma), store transposed: Ssh[r][tok]
    #pragma unroll
    for (int i = 0; i < 8; ++i) {
        float c = cw_s[ty*8 + i];
        #pragma unroll
        for (int j = 0; j < 8; ++j) {
            float v = acc[i][j];
            float s = v / (1.f + __expf(-v));
            Ssh[(tx*8 + j)*132 + ty*8 + i] = s * c;
        }
    }
    __syncthreads();

    // ---- Phase 2: down-projection, 16 d-tiles of 128, K = 128 ----
    const float* Ve = V + (size_t)e * DM * RR;
    float* Vs = Bs;
    for (int dt = 0; dt < 16; ++dt) {
        #pragma unroll
        for (int i = 0; i < 8; ++i)
            #pragma unroll
            for (int j = 0; j < 8; ++j) acc[i][j] = 0.f;

        const float* v0p = Ve + (size_t)(dt*128 + lrow)      * RR + lk;
        const float* v1p = Ve + (size_t)(dt*128 + lrow + 64) * RR + lk;

        for (int kc = 0; kc < RR; kc += 16) {
            float4 a = *(const float4*)(v0p + kc);
            float4 b = *(const float4*)(v1p + kc);
            Vs[(lk+0)*132 + lrow] = a.x; Vs[(lk+1)*132 + lrow] = a.y;
            Vs[(lk+2)*132 + lrow] = a.z; Vs[(lk+3)*132 + lrow] = a.w;
            Vs[(lk+0)*132 + lrow+64] = b.x; Vs[(lk+1)*132 + lrow+64] = b.y;
            Vs[(lk+2)*132 + lrow+64] = b.z; Vs[(lk+3)*132 + lrow+64] = b.w;
            __syncthreads();
            #pragma unroll
            for (int k = 0; k < 16; ++k) {
                float ra[8], rb[8];
                *(float4*)&ra[0] = *(const float4*)&Ssh[(kc+k)*132 + ty*8];
                *(float4*)&ra[4] = *(const float4*)&Ssh[(kc+k)*132 + ty*8 + 4];
                *(float4*)&rb[0] = *(const float4*)&Vs[k*132 + tx*8];
                *(float4*)&rb[4] = *(const float4*)&Vs[k*132 + tx*8 + 4];
                #pragma unroll
                for (int i = 0; i < 8; ++i)
                    #pragma unroll
                    for (int j = 0; j < 8; ++j)
                        acc[i][j] += ra[i] * rb[j];
            }
            __syncthreads();
        }

        #pragma unroll
        for (int i = 0; i < 8; ++i) {
            int rr_ = ty*8 + i;
            if (t0 + rr_ < n) {
                float* op = out + (size_t)tok_s[rr_] * DM + dt*128 + tx*8;
                #pragma unroll
                for (int j = 0; j < 8; ++j) atomicAdd(op + j, acc[i][j]);
            }
        }
    }
}

// ---------------------------------------------------------------------------
extern "C" void kernel_launch(void* const* d_in, const int* in_sizes, int n_in,
                              void* d_out, int out_size)
{
    const float* x    = (const float*)d_in[0];
    const float* Wenc = (const float*)d_in[1];
    const float* benc = (const float*)d_in[2];
    const float* Wg   = (const float*)d_in[3];
    const float* U    = (const float*)d_in[4];
    const float* V    = (const float*)d_in[5];
    const float* gm   = (const float*)d_in[6];
    float* out = (float*)d_out;

    cudaFuncSetAttribute(expert_kernel,
                         cudaFuncAttributeMaxDynamicSharedMemorySize,
                         EXP_SMEM_BYTES);

    encoder_gemm<<<dim3(DM/128, B_TOK/128), 256>>>(x, Wenc, benc, out);
    zero_counts<<<1, 32>>>();
    routing_kernel<<<B_TOK/16, 256>>>(Wg);
    expert_kernel<<<dim3(B_TOK/128, NEXP), 256, EXP_SMEM_BYTES>>>(U, V, gm, out);
}

// round 5
// speedup vs baseline: 1.5487x; 1.5487x over previous
#include <cuda_runtime.h>
#include <cuda_bf16.h>
#include <cstdint>

// FlashMoE round 5: encoder GEMM via legacy mma.sync (bf16 hi/lo 3-term split,
// fp32-class accuracy). tcgen05 unavailable: harness PTX target is compute_103.
// mma.sync/ldmatrix/cp.async compile for compute_103.

#define B_TOK 16384
#define DM    2048
#define NEXP  16
#define RR    128
#define CAP   16384

__device__ float         g_encoded[(size_t)B_TOK * DM];
__device__ int           g_cnt[NEXP];
__device__ int           g_tok[NEXP * CAP];
__device__ float         g_wgt[NEXP * CAP];
__device__ __nv_bfloat16 g_xh[(size_t)B_TOK * DM];
__device__ __nv_bfloat16 g_xl[(size_t)B_TOK * DM];
__device__ __nv_bfloat16 g_wh[(size_t)DM * DM];
__device__ __nv_bfloat16 g_wl[(size_t)DM * DM];

__device__ __forceinline__ uint32_t smem_u32(const void* p) {
    uint32_t a;
    asm("{ .reg .u64 t; cvta.to.shared.u64 t, %1; cvt.u32.u64 %0, t; }"
        : "=r"(a) : "l"(p));
    return a;
}
#define CP_ASYNC16(sm, gp) \
    asm volatile("cp.async.cg.shared.global [%0], [%1], 16;" :: "r"(sm), "l"(gp))
#define CP_COMMIT() asm volatile("cp.async.commit_group;" ::: "memory")
#define CP_WAIT1()  asm volatile("cp.async.wait_group 1;" ::: "memory")

__device__ __forceinline__ void ldm_x4(uint32_t* r, uint32_t addr) {
    asm volatile("ldmatrix.sync.aligned.m8n8.x4.shared.b16 {%0,%1,%2,%3}, [%4];"
                 : "=r"(r[0]), "=r"(r[1]), "=r"(r[2]), "=r"(r[3]) : "r"(addr));
}
__device__ __forceinline__ void mma_bf16(float* c, const uint32_t* a, const uint32_t* b) {
    asm volatile(
        "mma.sync.aligned.m16n8k16.row.col.f32.bf16.bf16.f32 "
        "{%0,%1,%2,%3}, {%4,%5,%6,%7}, {%8,%9}, {%0,%1,%2,%3};"
        : "+f"(c[0]), "+f"(c[1]), "+f"(c[2]), "+f"(c[3])
        : "r"(a[0]), "r"(a[1]), "r"(a[2]), "r"(a[3]), "r"(b[0]), "r"(b[1]));
}

__global__ __launch_bounds__(256) void split_bf16(
    const float* __restrict__ src, __nv_bfloat16* __restrict__ hi,
    __nv_bfloat16* __restrict__ lo, int n)
{
    int i = (blockIdx.x * blockDim.x + threadIdx.x) * 4;
    if (i >= n) return;
    float4 v = *(const float4*)(src + i);
    __nv_bfloat16 h0 = __float2bfloat16(v.x), h1 = __float2bfloat16(v.y);
    __nv_bfloat16 h2 = __float2bfloat16(v.z), h3 = __float2bfloat16(v.w);
    __nv_bfloat16 l0 = __float2bfloat16(v.x - __bfloat162float(h0));
    __nv_bfloat16 l1 = __float2bfloat16(v.y - __bfloat162float(h1));
    __nv_bfloat16 l2 = __float2bfloat16(v.z - __bfloat162float(h2));
    __nv_bfloat16 l3 = __float2bfloat16(v.w - __bfloat162float(h3));
    __nv_bfloat162* hp = (__nv_bfloat162*)(hi + i);
    __nv_bfloat162* lp = (__nv_bfloat162*)(lo + i);
    hp[0] = __nv_bfloat162(h0, h1); hp[1] = __nv_bfloat162(h2, h3);
    lp[0] = __nv_bfloat162(l0, l1); lp[1] = __nv_bfloat162(l2, l3);
}

// ===========================================================================
// Encoder: 128x128 C-tile, BK=32 double-buffered cp.async, 8 warps (32m x 64n).
// Smem rows 80B-strided (64B data + 16B pad) -> conflict-free ldmatrix.
// ===========================================================================
#define BK        32
#define N_CHUNK   (DM / BK)        // 64
#define ROW_B     80
#define TILE_B    (128 * ROW_B)    // 10240
#define BUF_B     (4 * TILE_B)     // 40960
#define ENC_SMEM  (2 * BUF_B)      // 81920

__global__ __launch_bounds__(256) void encoder_mma(
    const float* __restrict__ bias, float* __restrict__ out)
{
    extern __shared__ char smc[];
    const uint32_t sbase = smem_u32(smc);
    const int tid  = threadIdx.x;
    const int wid  = tid >> 5;
    const int lane = tid & 31;
    const int rowBase = blockIdx.y * 128;
    const int colBase = blockIdx.x * 128;
    const int warp_m = (wid & 3) * 32;
    const int warp_n = (wid >> 2) * 64;

    const int ldrow = tid >> 1;
    const int ldc0  = (tid & 1) * 2;
    const uint32_t srow_off = (uint32_t)(ldrow * ROW_B + ldc0 * 16);

    const __nv_bfloat16* gah = g_xh + (size_t)(rowBase + ldrow) * DM + ldc0 * 8;
    const __nv_bfloat16* gal = g_xl + (size_t)(rowBase + ldrow) * DM + ldc0 * 8;
    const __nv_bfloat16* gbh = g_wh + (size_t)(colBase + ldrow) * DM + ldc0 * 8;
    const __nv_bfloat16* gbl = g_wl + (size_t)(colBase + ldrow) * DM + ldc0 * 8;

    float c[2][8][4];
    #pragma unroll
    for (int mi = 0; mi < 2; ++mi)
        #pragma unroll
        for (int ni = 0; ni < 8; ++ni)
            #pragma unroll
            for (int q = 0; q < 4; ++q) c[mi][ni][q] = 0.f;

    const int a_r = lane & 15;
    const int a_k = (lane >> 4) * 8;
    const int b_r = ((lane >> 4) << 3) + (lane & 7);
    const int b_k = ((lane >> 3) & 1) * 8;

    auto issue_loads = [&](int chunk, int buf) {
        const uint32_t s0 = sbase + buf * BUF_B + srow_off;
        const size_t gofs = (size_t)chunk * BK;
        CP_ASYNC16(s0 + 0 * TILE_B,      gah + gofs);
        CP_ASYNC16(s0 + 0 * TILE_B + 16, gah + gofs + 8);
        CP_ASYNC16(s0 + 1 * TILE_B,      gal + gofs);
        CP_ASYNC16(s0 + 1 * TILE_B + 16, gal + gofs + 8);
        CP_ASYNC16(s0 + 2 * TILE_B,      gbh + gofs);
        CP_ASYNC16(s0 + 2 * TILE_B + 16, gbh + gofs + 8);
        CP_ASYNC16(s0 + 3 * TILE_B,      gbl + gofs);
        CP_ASYNC16(s0 + 3 * TILE_B + 16, gbl + gofs + 8);
        CP_COMMIT();
    };

    issue_loads(0, 0);

    for (int chunk = 0; chunk < N_CHUNK; ++chunk) {
        const int buf = chunk & 1;
        if (chunk + 1 < N_CHUNK) issue_loads(chunk + 1, buf ^ 1);
        CP_WAIT1();
        __syncthreads();

        const uint32_t tb = sbase + buf * BUF_B;
        #pragma unroll
        for (int ks = 0; ks < 2; ++ks) {
            uint32_t ah[2][4], al[2][4], bh[4][4], bl[4][4];
            #pragma unroll
            for (int mi = 0; mi < 2; ++mi) {
                uint32_t ao = (uint32_t)((warp_m + mi * 16 + a_r) * ROW_B
                                         + (ks * 16 + a_k) * 2);
                ldm_x4(ah[mi], tb + 0 * TILE_B + ao);
                ldm_x4(al[mi], tb + 1 * TILE_B + ao);
            }
            #pragma unroll
            for (int nb = 0; nb < 4; ++nb) {
                uint32_t bo = (uint32_t)((warp_n + nb * 16 + b_r) * ROW_B
                                         + (ks * 16 + b_k) * 2);
                ldm_x4(bh[nb], tb + 2 * TILE_B + bo);  // [0,1]=n8lo frag, [2,3]=n8hi frag
                ldm_x4(bl[nb], tb + 3 * TILE_B + bo);
            }
            #pragma unroll
            for (int mi = 0; mi < 2; ++mi)
                #pragma unroll
                for (int nb = 0; nb < 4; ++nb) {
                    mma_bf16(c[mi][nb*2],   ah[mi], &bh[nb][0]);
                    mma_bf16(c[mi][nb*2],   ah[mi], &bl[nb][0]);
                    mma_bf16(c[mi][nb*2],   al[mi], &bh[nb][0]);
                    mma_bf16(c[mi][nb*2+1], ah[mi], &bh[nb][2]);
                    mma_bf16(c[mi][nb*2+1], ah[mi], &bl[nb][2]);
                    mma_bf16(c[mi][nb*2+1], al[mi], &bh[nb][2]);
                }
        }
        __syncthreads();
    }

    const int erow = rowBase + warp_m + (lane >> 2);
    const int ecol0 = colBase + warp_n + (lane & 3) * 2;
    #pragma unroll
    for (int mi = 0; mi < 2; ++mi) {
        #pragma unroll
        for (int ni = 0; ni < 8; ++ni) {
            int col = ecol0 + ni * 8;
            float b0 = bias[col], b1 = bias[col + 1];
            int r0 = erow + mi * 16;
            float2 v0 = make_float2(c[mi][ni][0] + b0, c[mi][ni][1] + b1);
            float2 v1 = make_float2(c[mi][ni][2] + b0, c[mi][ni][3] + b1);
            size_t o0 = (size_t)r0 * DM + col;
            size_t o1 = (size_t)(r0 + 8) * DM + col;
            *(float2*)(g_encoded + o0) = v0;
            *(float2*)(out       + o0) = v0;
            *(float2*)(g_encoded + o1) = v1;
            *(float2*)(out       + o1) = v1;
        }
    }
}

__global__ void zero_counts()
{
    if (threadIdx.x < NEXP) g_cnt[threadIdx.x] = 0;
}

__global__ __launch_bounds__(256) void routing_kernel(
    const float* __restrict__ Wg)
{
    const int warp = (blockIdx.x * blockDim.x + threadIdx.x) >> 5;
    const int lane = threadIdx.x & 31;
    const int b0 = warp * 2;
    if (b0 >= B_TOK) return;

    const float4* x0 = (const float4*)(g_encoded + (size_t)b0 * DM);
    const float4* x1 = (const float4*)(g_encoded + (size_t)(b0 + 1) * DM);
    const float4* wg = (const float4*)Wg;

    float a0[NEXP], a1[NEXP];
    #pragma unroll
    for (int m = 0; m < NEXP; ++m) { a0[m] = 0.f; a1[m] = 0.f; }

    for (int it = 0; it < DM / 128; ++it) {
        int d4 = it * 32 + lane;
        float4 v0 = x0[d4];
        float4 v1 = x1[d4];
        #pragma unroll
        for (int m = 0; m < NEXP; ++m) {
            float4 w = wg[m * (DM / 4) + d4];
            a0[m] += v0.x*w.x + v0.y*w.y + v0.z*w.z + v0.w*w.w;
            a1[m] += v1.x*w.x + v1.y*w.y + v1.z*w.z + v1.w*w.w;
        }
    }
    #pragma unroll
    for (int m = 0; m < NEXP; ++m) {
        #pragma unroll
        for (int off = 16; off > 0; off >>= 1) {
            a0[m] += __shfl_xor_sync(0xffffffffu, a0[m], off);
            a1[m] += __shfl_xor_sync(0xffffffffu, a1[m], off);
        }
    }
    if (lane < 2) {
        float v[NEXP];
        #pragma unroll
        for (int m = 0; m < NEXP; ++m) v[m] = (lane == 0) ? a0[m] : a1[m];
        const int b = b0 + lane;

        float best = v[0]; int bi = 0;
        #pragma unroll
        for (int m = 1; m < NEXP; ++m)
            if (v[m] > best) { best = v[m]; bi = m; }
        float best2 = -3.402823466e38f; int bi2 = 0;
        #pragma unroll
        for (int m = 0; m < NEXP; ++m)
            if (m != bi && v[m] > best2) { best2 = v[m]; bi2 = m; }

        float e2 = __expf(best2 - best);
        float denom = 1.f + e2 + 1e-12f;
        float w1 = 1.f / denom;
        float w2 = e2 / denom;
        if (w1 > 1e-12f) {
            int p = atomicAdd(&g_cnt[bi], 1);
            g_tok[bi * CAP + p] = b; g_wgt[bi * CAP + p] = w1;
        }
        if (w2 > 1e-12f) {
            int p = atomicAdd(&g_cnt[bi2], 1);
            g_tok[bi2 * CAP + p] = b; g_wgt[bi2 * CAP + p] = w2;
        }
    }
}

#define EXP_SMEM_BYTES ((2*16*132 + 128*132) * 4)

__global__ __launch_bounds__(256) void expert_kernel(
    const float* __restrict__ U, const float* __restrict__ V,
    const float* __restrict__ gamma, float* __restrict__ out)
{
    const int e = blockIdx.y;
    const int n = g_cnt[e];
    const int t0 = blockIdx.x * 128;
    if (t0 >= n) return;

    extern __shared__ float smf[];
    float* As  = smf;
    float* Bs  = smf + 16 * 132;
    float* Ssh = smf + 2 * 16 * 132;
    __shared__ int   tok_s[128];
    __shared__ float cw_s[128];

    const int tid = threadIdx.x;
    if (tid < 128) {
        int idx = t0 + tid;
        if (idx < n) {
            tok_s[tid] = g_tok[e * CAP + idx];
            cw_s[tid]  = g_wgt[e * CAP + idx] * gamma[e];
        } else {
            tok_s[tid] = 0;
            cw_s[tid]  = 0.f;
        }
    }
    __syncthreads();

    const int tx = tid & 15;
    const int ty = tid >> 4;
    const int lrow = tid >> 2;
    const int lk   = (tid & 3) << 2;

    const float* ar0 = g_encoded + (size_t)tok_s[lrow]      * DM + lk;
    const float* ar1 = g_encoded + (size_t)tok_s[lrow + 64] * DM + lk;
    const float* Ue  = U + (size_t)e * RR * DM;
    const float* u0  = Ue + (size_t)lrow        * DM + lk;
    const float* u1  = Ue + (size_t)(lrow + 64) * DM + lk;

    float acc[8][8];
    #pragma unroll
    for (int i = 0; i < 8; ++i)
        #pragma unroll
        for (int j = 0; j < 8; ++j) acc[i][j] = 0.f;

    for (int kt = 0; kt < DM; kt += 16) {
        float4 av0 = *(const float4*)(ar0 + kt);
        float4 av1 = *(const float4*)(ar1 + kt);
        float4 bv0 = *(const float4*)(u0 + kt);
        float4 bv1 = *(const float4*)(u1 + kt);
        As[(lk+0)*132 + lrow] = av0.x; As[(lk+1)*132 + lrow] = av0.y;
        As[(lk+2)*132 + lrow] = av0.z; As[(lk+3)*132 + lrow] = av0.w;
        As[(lk+0)*132 + lrow+64] = av1.x; As[(lk+1)*132 + lrow+64] = av1.y;
        As[(lk+2)*132 + lrow+64] = av1.z; As[(lk+3)*132 + lrow+64] = av1.w;
        Bs[(lk+0)*132 + lrow] = bv0.x; Bs[(lk+1)*132 + lrow] = bv0.y;
        Bs[(lk+2)*132 + lrow] = bv0.z; Bs[(lk+3)*132 + lrow] = bv0.w;
        Bs[(lk+0)*132 + lrow+64] = bv1.x; Bs[(lk+1)*132 + lrow+64] = bv1.y;
        Bs[(lk+2)*132 + lrow+64] = bv1.z; Bs[(lk+3)*132 + lrow+64] = bv1.w;
        __syncthreads();
        #pragma unroll
        for (int k = 0; k < 16; ++k) {
            float ra[8], rb[8];
            *(float4*)&ra[0] = *(const float4*)&As[k*132 + ty*8];
            *(float4*)&ra[4] = *(const float4*)&As[k*132 + ty*8 + 4];
            *(float4*)&rb[0] = *(const float4*)&Bs[k*132 + tx*8];
            *(float4*)&rb[4] = *(const float4*)&Bs[k*132 + tx*8 + 4];
            #pragma unroll
            for (int i = 0; i < 8; ++i)
                #pragma unroll
                for (int j = 0; j < 8; ++j)
                    acc[i][j] += ra[i] * rb[j];
        }
        __syncthreads();
    }

    #pragma unroll
    for (int i = 0; i < 8; ++i) {
        float cc = cw_s[ty*8 + i];
        #pragma unroll
        for (int j = 0; j < 8; ++j) {
            float v = acc[i][j];
            float s = v / (1.f + __expf(-v));
            Ssh[(tx*8 + j)*132 + ty*8 + i] = s * cc;
        }
    }
    __syncthreads();

    const float* Ve = V + (size_t)e * DM * RR;
    float* Vs = Bs;
    for (int dt = 0; dt < 16; ++dt) {
        #pragma unroll
        for (int i = 0; i < 8; ++i)
            #pragma unroll
            for (int j = 0; j < 8; ++j) acc[i][j] = 0.f;

        const float* v0p = Ve + (size_t)(dt*128 + lrow)      * RR + lk;
        const float* v1p = Ve + (size_t)(dt*128 + lrow + 64) * RR + lk;

        for (int kc = 0; kc < RR; kc += 16) {
            float4 a = *(const float4*)(v0p + kc);
            float4 b = *(const float4*)(v1p + kc);
            Vs[(lk+0)*132 + lrow] = a.x; Vs[(lk+1)*132 + lrow] = a.y;
            Vs[(lk+2)*132 + lrow] = a.z; Vs[(lk+3)*132 + lrow] = a.w;
            Vs[(lk+0)*132 + lrow+64] = b.x; Vs[(lk+1)*132 + lrow+64] = b.y;
            Vs[(lk+2)*132 + lrow+64] = b.z; Vs[(lk+3)*132 + lrow+64] = b.w;
            __syncthreads();
            #pragma unroll
            for (int k = 0; k < 16; ++k) {
                float ra[8], rb[8];
                *(float4*)&ra[0] = *(const float4*)&Ssh[(kc+k)*132 + ty*8];
                *(float4*)&ra[4] = *(const float4*)&Ssh[(kc+k)*132 + ty*8 + 4];
                *(float4*)&rb[0] = *(const float4*)&Vs[k*132 + tx*8];
                *(float4*)&rb[4] = *(const float4*)&Vs[k*132 + tx*8 + 4];
                #pragma unroll
                for (int i = 0; i < 8; ++i)
                    #pragma unroll
                    for (int j = 0; j < 8; ++j)
                        acc[i][j] += ra[i] * rb[j];
            }
            __syncthreads();
        }

        #pragma unroll
        for (int i = 0; i < 8; ++i) {
            int rr_ = ty*8 + i;
            if (t0 + rr_ < n) {
                float* op = out + (size_t)tok_s[rr_] * DM + dt*128 + tx*8;
                #pragma unroll
                for (int j = 0; j < 8; ++j) atomicAdd(op + j, acc[i][j]);
            }
        }
    }
}

extern "C" void kernel_launch(void* const* d_in, const int* in_sizes, int n_in,
                              void* d_out, int out_size)
{
    const float* x    = (const float*)d_in[0];
    const float* Wenc = (const float*)d_in[1];
    const float* benc = (const float*)d_in[2];
    const float* Wg   = (const float*)d_in[3];
    const float* U    = (const float*)d_in[4];
    const float* V    = (const float*)d_in[5];
    const float* gm   = (const float*)d_in[6];
    float* out = (float*)d_out;

    cudaFuncSetAttribute(expert_kernel,
                         cudaFuncAttributeMaxDynamicSharedMemorySize,
                         EXP_SMEM_BYTES);
    cudaFuncSetAttribute(encoder_mma,
                         cudaFuncAttributeMaxDynamicSharedMemorySize,
                         ENC_SMEM);

    __nv_bfloat16 *xh, *xl, *wh, *wl;
    cudaGetSymbolAddress((void**)&xh, g_xh);
    cudaGetSymbolAddress((void**)&xl, g_xl);
    cudaGetSymbolAddress((void**)&wh, g_wh);
    cudaGetSymbolAddress((void**)&wl, g_wl);

    const int nx = B_TOK * DM, nw = DM * DM;
    split_bf16<<<(nx/4 + 255)/256, 256>>>(x, xh, xl, nx);
    split_bf16<<<(nw/4 + 255)/256, 256>>>(Wenc, wh, wl, nw);
    encoder_mma<<<dim3(DM/128, B_TOK/128), 256, ENC_SMEM>>>(benc, out);
    zero_counts<<<1, 32>>>();
    routing_kernel<<<B_TOK/16, 256>>>(Wg);
    expert_kernel<<<dim3(B_TOK/128, NEXP), 256, EXP_SMEM_BYTES>>>(U, V, gm, out);
}

// round 6
// speedup vs baseline: 2.2184x; 1.4324x over previous
#include <cuda_runtime.h>
#include <cuda_bf16.h>
#include <cstdint>

// FlashMoE round 6: encoder AND expert GEMMs via legacy mma.sync
// (bf16 hi/lo 3-term split -> fp32-class accuracy). tcgen05 unavailable
// (harness PTX target compute_103 rejects it).
//
// Pipeline:
//   0) split_bf16 x4: x, W_enc, U, V -> bf16 (hi, lo) pairs
//   1) encoder_mma: enc = x @ W_enc^T + b  -> g_encoded (fp32), g_eh/g_el (bf16
//      split), out (fp32 base)
//   2) zero_counts
//   3) routing_kernel: logits = enc @ Wg^T, top-2, softmax, per-expert lists
//   4) expert_mma: per (expert, 128-token tile):
//      phase1: S = silu(gather(enc) @ U_e^T) * (w*gamma)  [mma, K=2048]
//      phase2: delta = S @ V_e^T per 128-d tile           [mma, K=128]
//      atomicAdd into out.

#define B_TOK 16384
#define DM    2048
#define NEXP  16
#define RR    128
#define CAP   16384

__device__ float         g_encoded[(size_t)B_TOK * DM];
__device__ int           g_cnt[NEXP];
__device__ int           g_tok[NEXP * CAP];
__device__ float         g_wgt[NEXP * CAP];
__device__ __nv_bfloat16 g_xh[(size_t)B_TOK * DM];
__device__ __nv_bfloat16 g_xl[(size_t)B_TOK * DM];
__device__ __nv_bfloat16 g_wh[(size_t)DM * DM];
__device__ __nv_bfloat16 g_wl[(size_t)DM * DM];
__device__ __nv_bfloat16 g_eh[(size_t)B_TOK * DM];
__device__ __nv_bfloat16 g_el[(size_t)B_TOK * DM];
__device__ __nv_bfloat16 g_uh[(size_t)NEXP * RR * DM];
__device__ __nv_bfloat16 g_ul[(size_t)NEXP * RR * DM];
__device__ __nv_bfloat16 g_vh[(size_t)NEXP * DM * RR];
__device__ __nv_bfloat16 g_vl[(size_t)NEXP * DM * RR];

__device__ __forceinline__ uint32_t smem_u32(const void* p) {
    uint32_t a;
    asm("{ .reg .u64 t; cvta.to.shared.u64 t, %1; cvt.u32.u64 %0, t; }"
        : "=r"(a) : "l"(p));
    return a;
}
#define CP_ASYNC16(sm, gp) \
    asm volatile("cp.async.cg.shared.global [%0], [%1], 16;" :: "r"(sm), "l"(gp))
#define CP_COMMIT() asm volatile("cp.async.commit_group;" ::: "memory")
#define CP_WAIT1()  asm volatile("cp.async.wait_group 1;" ::: "memory")
#define CP_WAIT0()  asm volatile("cp.async.wait_group 0;" ::: "memory")

__device__ __forceinline__ void ldm_x4(uint32_t* r, uint32_t addr) {
    asm volatile("ldmatrix.sync.aligned.m8n8.x4.shared.b16 {%0,%1,%2,%3}, [%4];"
                 : "=r"(r[0]), "=r"(r[1]), "=r"(r[2]), "=r"(r[3]) : "r"(addr));
}
__device__ __forceinline__ void mma_bf16(float* c, const uint32_t* a, const uint32_t* b) {
    asm volatile(
        "mma.sync.aligned.m16n8k16.row.col.f32.bf16.bf16.f32 "
        "{%0,%1,%2,%3}, {%4,%5,%6,%7}, {%8,%9}, {%0,%1,%2,%3};"
        : "+f"(c[0]), "+f"(c[1]), "+f"(c[2]), "+f"(c[3])
        : "r"(a[0]), "r"(a[1]), "r"(a[2]), "r"(a[3]), "r"(b[0]), "r"(b[1]));
}

__global__ __launch_bounds__(256) void split_bf16(
    const float* __restrict__ src, __nv_bfloat16* __restrict__ hi,
    __nv_bfloat16* __restrict__ lo, int n)
{
    int i = (blockIdx.x * blockDim.x + threadIdx.x) * 4;
    if (i >= n) return;
    float4 v = *(const float4*)(src + i);
    __nv_bfloat16 h0 = __float2bfloat16(v.x), h1 = __float2bfloat16(v.y);
    __nv_bfloat16 h2 = __float2bfloat16(v.z), h3 = __float2bfloat16(v.w);
    __nv_bfloat16 l0 = __float2bfloat16(v.x - __bfloat162float(h0));
    __nv_bfloat16 l1 = __float2bfloat16(v.y - __bfloat162float(h1));
    __nv_bfloat16 l2 = __float2bfloat16(v.z - __bfloat162float(h2));
    __nv_bfloat16 l3 = __float2bfloat16(v.w - __bfloat162float(h3));
    __nv_bfloat162* hp = (__nv_bfloat162*)(hi + i);
    __nv_bfloat162* lp = (__nv_bfloat162*)(lo + i);
    hp[0] = __nv_bfloat162(h0, h1); hp[1] = __nv_bfloat162(h2, h3);
    lp[0] = __nv_bfloat162(l0, l1); lp[1] = __nv_bfloat162(l2, l3);
}

// ===========================================================================
// Encoder: 128x128 C-tile, BK=32 double-buffered cp.async, 8 warps (32m x 64n).
// Smem rows 80B-strided -> conflict-free ldmatrix.
// ===========================================================================
#define BK        32
#define N_CHUNK   (DM / BK)        // 64
#define ROW_B     80
#define TILE_B    (128 * ROW_B)    // 10240
#define BUF_B     (4 * TILE_B)     // 40960
#define ENC_SMEM  (2 * BUF_B)      // 81920

__global__ __launch_bounds__(256) void encoder_mma(
    const float* __restrict__ bias, float* __restrict__ out)
{
    extern __shared__ char smc[];
    const uint32_t sbase = smem_u32(smc);
    const int tid  = threadIdx.x;
    const int wid  = tid >> 5;
    const int lane = tid & 31;
    const int rowBase = blockIdx.y * 128;
    const int colBase = blockIdx.x * 128;
    const int warp_m = (wid & 3) * 32;
    const int warp_n = (wid >> 2) * 64;

    const int ldrow = tid >> 1;
    const int ldc0  = (tid & 1) * 2;
    const uint32_t srow_off = (uint32_t)(ldrow * ROW_B + ldc0 * 16);

    const __nv_bfloat16* gah = g_xh + (size_t)(rowBase + ldrow) * DM + ldc0 * 8;
    const __nv_bfloat16* gal = g_xl + (size_t)(rowBase + ldrow) * DM + ldc0 * 8;
    const __nv_bfloat16* gbh = g_wh + (size_t)(colBase + ldrow) * DM + ldc0 * 8;
    const __nv_bfloat16* gbl = g_wl + (size_t)(colBase + ldrow) * DM + ldc0 * 8;

    float c[2][8][4];
    #pragma unroll
    for (int mi = 0; mi < 2; ++mi)
        #pragma unroll
        for (int ni = 0; ni < 8; ++ni)
            #pragma unroll
            for (int q = 0; q < 4; ++q) c[mi][ni][q] = 0.f;

    const int a_r = lane & 15;
    const int a_k = (lane >> 4) * 8;
    const int b_r = ((lane >> 4) << 3) + (lane & 7);
    const int b_k = ((lane >> 3) & 1) * 8;

    auto issue_loads = [&](int chunk, int buf) {
        const uint32_t s0 = sbase + buf * BUF_B + srow_off;
        const size_t gofs = (size_t)chunk * BK;
        CP_ASYNC16(s0 + 0 * TILE_B,      gah + gofs);
        CP_ASYNC16(s0 + 0 * TILE_B + 16, gah + gofs + 8);
        CP_ASYNC16(s0 + 1 * TILE_B,      gal + gofs);
        CP_ASYNC16(s0 + 1 * TILE_B + 16, gal + gofs + 8);
        CP_ASYNC16(s0 + 2 * TILE_B,      gbh + gofs);
        CP_ASYNC16(s0 + 2 * TILE_B + 16, gbh + gofs + 8);
        CP_ASYNC16(s0 + 3 * TILE_B,      gbl + gofs);
        CP_ASYNC16(s0 + 3 * TILE_B + 16, gbl + gofs + 8);
        CP_COMMIT();
    };

    issue_loads(0, 0);

    for (int chunk = 0; chunk < N_CHUNK; ++chunk) {
        const int buf = chunk & 1;
        if (chunk + 1 < N_CHUNK) { issue_loads(chunk + 1, buf ^ 1); CP_WAIT1(); }
        else                     { CP_WAIT0(); }
        __syncthreads();

        const uint32_t tb = sbase + buf * BUF_B;
        #pragma unroll
        for (int ks = 0; ks < 2; ++ks) {
            uint32_t ah[2][4], al[2][4], bh[4][4], bl[4][4];
            #pragma unroll
            for (int mi = 0; mi < 2; ++mi) {
                uint32_t ao = (uint32_t)((warp_m + mi * 16 + a_r) * ROW_B
                                         + (ks * 16 + a_k) * 2);
                ldm_x4(ah[mi], tb + 0 * TILE_B + ao);
                ldm_x4(al[mi], tb + 1 * TILE_B + ao);
            }
            #pragma unroll
            for (int nb = 0; nb < 4; ++nb) {
                uint32_t bo = (uint32_t)((warp_n + nb * 16 + b_r) * ROW_B
                                         + (ks * 16 + b_k) * 2);
                ldm_x4(bh[nb], tb + 2 * TILE_B + bo);
                ldm_x4(bl[nb], tb + 3 * TILE_B + bo);
            }
            #pragma unroll
            for (int mi = 0; mi < 2; ++mi)
                #pragma unroll
                for (int nb = 0; nb < 4; ++nb) {
                    mma_bf16(c[mi][nb*2],   ah[mi], &bh[nb][0]);
                    mma_bf16(c[mi][nb*2],   ah[mi], &bl[nb][0]);
                    mma_bf16(c[mi][nb*2],   al[mi], &bh[nb][0]);
                    mma_bf16(c[mi][nb*2+1], ah[mi], &bh[nb][2]);
                    mma_bf16(c[mi][nb*2+1], ah[mi], &bl[nb][2]);
                    mma_bf16(c[mi][nb*2+1], al[mi], &bh[nb][2]);
                }
        }
        __syncthreads();
    }

    // epilogue: bias + fp32 stores + bf16 hi/lo split of encoded
    const int erow = rowBase + warp_m + (lane >> 2);
    const int ecol0 = colBase + warp_n + (lane & 3) * 2;
    #pragma unroll
    for (int mi = 0; mi < 2; ++mi) {
        #pragma unroll
        for (int ni = 0; ni < 8; ++ni) {
            int col = ecol0 + ni * 8;
            float b0 = bias[col], b1 = bias[col + 1];
            int r0 = erow + mi * 16;
            float v00 = c[mi][ni][0] + b0, v01 = c[mi][ni][1] + b1;
            float v10 = c[mi][ni][2] + b0, v11 = c[mi][ni][3] + b1;
            size_t o0 = (size_t)r0 * DM + col;
            size_t o1 = (size_t)(r0 + 8) * DM + col;
            *(float2*)(g_encoded + o0) = make_float2(v00, v01);
            *(float2*)(out       + o0) = make_float2(v00, v01);
            *(float2*)(g_encoded + o1) = make_float2(v10, v11);
            *(float2*)(out       + o1) = make_float2(v10, v11);
            __nv_bfloat16 h00 = __float2bfloat16(v00), h01 = __float2bfloat16(v01);
            __nv_bfloat16 h10 = __float2bfloat16(v10), h11 = __float2bfloat16(v11);
            *(__nv_bfloat162*)(g_eh + o0) = __nv_bfloat162(h00, h01);
            *(__nv_bfloat162*)(g_eh + o1) = __nv_bfloat162(h10, h11);
            *(__nv_bfloat162*)(g_el + o0) = __nv_bfloat162(
                __float2bfloat16(v00 - __bfloat162float(h00)),
                __float2bfloat16(v01 - __bfloat162float(h01)));
            *(__nv_bfloat162*)(g_el + o1) = __nv_bfloat162(
                __float2bfloat16(v10 - __bfloat162float(h10)),
                __float2bfloat16(v11 - __bfloat162float(h11)));
        }
    }
}

__global__ void zero_counts()
{
    if (threadIdx.x < NEXP) g_cnt[threadIdx.x] = 0;
}

__global__ __launch_bounds__(256) void routing_kernel(
    const float* __restrict__ Wg)
{
    const int warp = (blockIdx.x * blockDim.x + threadIdx.x) >> 5;
    const int lane = threadIdx.x & 31;
    const int b0 = warp * 2;
    if (b0 >= B_TOK) return;

    const float4* x0 = (const float4*)(g_encoded + (size_t)b0 * DM);
    const float4* x1 = (const float4*)(g_encoded + (size_t)(b0 + 1) * DM);
    const float4* wg = (const float4*)Wg;

    float a0[NEXP], a1[NEXP];
    #pragma unroll
    for (int m = 0; m < NEXP; ++m) { a0[m] = 0.f; a1[m] = 0.f; }

    for (int it = 0; it < DM / 128; ++it) {
        int d4 = it * 32 + lane;
        float4 v0 = x0[d4];
        float4 v1 = x1[d4];
        #pragma unroll
        for (int m = 0; m < NEXP; ++m) {
            float4 w = wg[m * (DM / 4) + d4];
            a0[m] += v0.x*w.x + v0.y*w.y + v0.z*w.z + v0.w*w.w;
            a1[m] += v1.x*w.x + v1.y*w.y + v1.z*w.z + v1.w*w.w;
        }
    }
    #pragma unroll
    for (int m = 0; m < NEXP; ++m) {
        #pragma unroll
        for (int off = 16; off > 0; off >>= 1) {
            a0[m] += __shfl_xor_sync(0xffffffffu, a0[m], off);
            a1[m] += __shfl_xor_sync(0xffffffffu, a1[m], off);
        }
    }
    if (lane < 2) {
        float v[NEXP];
        #pragma unroll
        for (int m = 0; m < NEXP; ++m) v[m] = (lane == 0) ? a0[m] : a1[m];
        const int b = b0 + lane;

        float best = v[0]; int bi = 0;
        #pragma unroll
        for (int m = 1; m < NEXP; ++m)
            if (v[m] > best) { best = v[m]; bi = m; }
        float best2 = -3.402823466e38f; int bi2 = 0;
        #pragma unroll
        for (int m = 0; m < NEXP; ++m)
            if (m != bi && v[m] > best2) { best2 = v[m]; bi2 = m; }

        float e2 = __expf(best2 - best);
        float denom = 1.f + e2 + 1e-12f;
        float w1 = 1.f / denom;
        float w2 = e2 / denom;
        if (w1 > 1e-12f) {
            int p = atomicAdd(&g_cnt[bi], 1);
            g_tok[bi * CAP + p] = b; g_wgt[bi * CAP + p] = w1;
        }
        if (w2 > 1e-12f) {
            int p = atomicAdd(&g_cnt[bi2], 1);
            g_tok[bi2 * CAP + p] = b; g_wgt[bi2 * CAP + p] = w2;
        }
    }
}

// ===========================================================================
// Expert mma kernel. Block 256 thr, grid (128 token-tiles, 16 experts).
// Phase1: S[128tok x 128r] = silu(Agather @ U_e^T)*cw, K=2048 (3-term mma),
//         double-buffered like encoder. S re-split to bf16 hi/lo in smem
//         (rows 272B-strided: 256B data + 16B pad -> conflict-free ldmatrix).
// Phase2: per 128-wide d-tile: C = S @ Vtile^T, K=128 (3-term), atomicAdd out.
// ===========================================================================
#define ROW2_B   272
#define S_H_OFF  0
#define S_L_OFF  (128 * ROW2_B)          // 34816
#define V_H_OFF  (2 * 128 * ROW2_B)      // 69632
#define V_L_OFF  (3 * 128 * ROW2_B)      // 104448
#define EXPM_SMEM (4 * 128 * ROW2_B)     // 139264  (>= ENC-style phase1 81920)

__global__ __launch_bounds__(256) void expert_mma(
    const float* __restrict__ gamma, float* __restrict__ out)
{
    const int e = blockIdx.y;
    const int n = g_cnt[e];
    const int t0 = blockIdx.x * 128;
    if (t0 >= n) return;

    extern __shared__ char smc[];
    const uint32_t sbase = smem_u32(smc);
    __shared__ int   tok_s[128];
    __shared__ float cw_s[128];

    const int tid  = threadIdx.x;
    const int wid  = tid >> 5;
    const int lane = tid & 31;
    if (tid < 128) {
        int idx = t0 + tid;
        if (idx < n) {
            tok_s[tid] = g_tok[e * CAP + idx];
            cw_s[tid]  = g_wgt[e * CAP + idx] * gamma[e];
        } else {
            tok_s[tid] = 0;
            cw_s[tid]  = 0.f;
        }
    }
    __syncthreads();

    const int warp_m = (wid & 3) * 32;
    const int warp_n = (wid >> 2) * 64;
    const int a_r = lane & 15;
    const int a_k = (lane >> 4) * 8;
    const int b_r = ((lane >> 4) << 3) + (lane & 7);
    const int b_k = ((lane >> 3) & 1) * 8;

    // ---------------- Phase 1: up-projection (K = 2048) ----------------
    {
        const int ldrow = tid >> 1;
        const int ldc0  = (tid & 1) * 2;
        const uint32_t srow_off = (uint32_t)(ldrow * ROW_B + ldc0 * 16);
        const size_t arow = (size_t)tok_s[ldrow] * DM + ldc0 * 8;
        const __nv_bfloat16* gah = g_eh + arow;
        const __nv_bfloat16* gal = g_el + arow;
        const size_t urow = (size_t)e * RR * DM + (size_t)ldrow * DM + ldc0 * 8;
        const __nv_bfloat16* gbh = g_uh + urow;
        const __nv_bfloat16* gbl = g_ul + urow;

        float c[2][8][4];
        #pragma unroll
        for (int mi = 0; mi < 2; ++mi)
            #pragma unroll
            for (int ni = 0; ni < 8; ++ni)
                #pragma unroll
                for (int q = 0; q < 4; ++q) c[mi][ni][q] = 0.f;

        auto issue_loads = [&](int chunk, int buf) {
            const uint32_t s0 = sbase + buf * BUF_B + srow_off;
            const size_t gofs = (size_t)chunk * BK;
            CP_ASYNC16(s0 + 0 * TILE_B,      gah + gofs);
            CP_ASYNC16(s0 + 0 * TILE_B + 16, gah + gofs + 8);
            CP_ASYNC16(s0 + 1 * TILE_B,      gal + gofs);
            CP_ASYNC16(s0 + 1 * TILE_B + 16, gal + gofs + 8);
            CP_ASYNC16(s0 + 2 * TILE_B,      gbh + gofs);
            CP_ASYNC16(s0 + 2 * TILE_B + 16, gbh + gofs + 8);
            CP_ASYNC16(s0 + 3 * TILE_B,      gbl + gofs);
            CP_ASYNC16(s0 + 3 * TILE_B + 16, gbl + gofs + 8);
            CP_COMMIT();
        };

        issue_loads(0, 0);
        for (int chunk = 0; chunk < N_CHUNK; ++chunk) {
            const int buf = chunk & 1;
            if (chunk + 1 < N_CHUNK) { issue_loads(chunk + 1, buf ^ 1); CP_WAIT1(); }
            else                     { CP_WAIT0(); }
            __syncthreads();

            const uint32_t tb = sbase + buf * BUF_B;
            #pragma unroll
            for (int ks = 0; ks < 2; ++ks) {
                uint32_t ah[2][4], al[2][4], bh[4][4], bl[4][4];
                #pragma unroll
                for (int mi = 0; mi < 2; ++mi) {
                    uint32_t ao = (uint32_t)((warp_m + mi * 16 + a_r) * ROW_B
                                             + (ks * 16 + a_k) * 2);
                    ldm_x4(ah[mi], tb + 0 * TILE_B + ao);
                    ldm_x4(al[mi], tb + 1 * TILE_B + ao);
                }
                #pragma unroll
                for (int nb = 0; nb < 4; ++nb) {
                    uint32_t bo = (uint32_t)((warp_n + nb * 16 + b_r) * ROW_B
                                             + (ks * 16 + b_k) * 2);
                    ldm_x4(bh[nb], tb + 2 * TILE_B + bo);
                    ldm_x4(bl[nb], tb + 3 * TILE_B + bo);
                }
                #pragma unroll
                for (int mi = 0; mi < 2; ++mi)
                    #pragma unroll
                    for (int nb = 0; nb < 4; ++nb) {
                        mma_bf16(c[mi][nb*2],   ah[mi], &bh[nb][0]);
                        mma_bf16(c[mi][nb*2],   ah[mi], &bl[nb][0]);
                        mma_bf16(c[mi][nb*2],   al[mi], &bh[nb][0]);
                        mma_bf16(c[mi][nb*2+1], ah[mi], &bh[nb][2]);
                        mma_bf16(c[mi][nb*2+1], ah[mi], &bl[nb][2]);
                        mma_bf16(c[mi][nb*2+1], al[mi], &bh[nb][2]);
                    }
            }
            __syncthreads();
        }

        // silu * cw, split to bf16 hi/lo, store S to smem
        const int er  = warp_m + (lane >> 2);
        const int ec0 = warp_n + (lane & 3) * 2;
        #pragma unroll
        for (int mi = 0; mi < 2; ++mi) {
            int r0 = er + mi * 16;
            int r1 = r0 + 8;
            float w0 = cw_s[r0], w1 = cw_s[r1];
            #pragma unroll
            for (int ni = 0; ni < 8; ++ni) {
                int col = ec0 + ni * 8;
                float x00 = c[mi][ni][0], x01 = c[mi][ni][1];
                float x10 = c[mi][ni][2], x11 = c[mi][ni][3];
                float v00 = x00 / (1.f + __expf(-x00)) * w0;
                float v01 = x01 / (1.f + __expf(-x01)) * w0;
                float v10 = x10 / (1.f + __expf(-x10)) * w1;
                float v11 = x11 / (1.f + __expf(-x11)) * w1;
                __nv_bfloat16 h00 = __float2bfloat16(v00), h01 = __float2bfloat16(v01);
                __nv_bfloat16 h10 = __float2bfloat16(v10), h11 = __float2bfloat16(v11);
                uint32_t o0 = (uint32_t)(r0 * ROW2_B + col * 2);
                uint32_t o1 = (uint32_t)(r1 * ROW2_B + col * 2);
                *(__nv_bfloat162*)(smc + S_H_OFF + o0) = __nv_bfloat162(h00, h01);
                *(__nv_bfloat162*)(smc + S_H_OFF + o1) = __nv_bfloat162(h10, h11);
                *(__nv_bfloat162*)(smc + S_L_OFF + o0) = __nv_bfloat162(
                    __float2bfloat16(v00 - __bfloat162float(h00)),
                    __float2bfloat16(v01 - __bfloat162float(h01)));
                *(__nv_bfloat162*)(smc + S_L_OFF + o1) = __nv_bfloat162(
                    __float2bfloat16(v10 - __bfloat162float(h10)),
                    __float2bfloat16(v11 - __bfloat162float(h11)));
            }
        }
    }
    __syncthreads();

    // ---------------- Phase 2: down-projection, 16 d-tiles (K = 128) --------
    const int vrow = tid >> 1;                  // 0..127 (d row within tile)
    const int vcb  = (tid & 1) * 8;             // chunk base (of 16 x 16B chunks)
    const size_t vbase = (size_t)e * DM * RR + (size_t)vrow * RR + vcb * 8;

    for (int dt = 0; dt < 16; ++dt) {
        // load V tile (single-buffered)
        const size_t go = vbase + (size_t)dt * 128 * RR;
        #pragma unroll
        for (int i = 0; i < 8; ++i) {
            uint32_t so = (uint32_t)(vrow * ROW2_B + (vcb + i) * 16);
            CP_ASYNC16(sbase + V_H_OFF + so, g_vh + go + i * 8);
            CP_ASYNC16(sbase + V_L_OFF + so, g_vl + go + i * 8);
        }
        CP_COMMIT();
        CP_WAIT0();
        __syncthreads();

        float c[2][8][4];
        #pragma unroll
        for (int mi = 0; mi < 2; ++mi)
            #pragma unroll
            for (int ni = 0; ni < 8; ++ni)
                #pragma unroll
                for (int q = 0; q < 4; ++q) c[mi][ni][q] = 0.f;

        #pragma unroll
        for (int ks = 0; ks < 8; ++ks) {
            uint32_t ah[2][4], al[2][4], bh[4][4], bl[4][4];
            #pragma unroll
            for (int mi = 0; mi < 2; ++mi) {
                uint32_t ao = (uint32_t)((warp_m + mi * 16 + a_r) * ROW2_B
                                         + (ks * 16 + a_k) * 2);
                ldm_x4(ah[mi], sbase + S_H_OFF + ao);
                ldm_x4(al[mi], sbase + S_L_OFF + ao);
            }
            #pragma unroll
            for (int nb = 0; nb < 4; ++nb) {
                uint32_t bo = (uint32_t)((warp_n + nb * 16 + b_r) * ROW2_B
                                         + (ks * 16 + b_k) * 2);
                ldm_x4(bh[nb], sbase + V_H_OFF + bo);
                ldm_x4(bl[nb], sbase + V_L_OFF + bo);
            }
            #pragma unroll
            for (int mi = 0; mi < 2; ++mi)
                #pragma unroll
                for (int nb = 0; nb < 4; ++nb) {
                    mma_bf16(c[mi][nb*2],   ah[mi], &bh[nb][0]);
                    mma_bf16(c[mi][nb*2],   ah[mi], &bl[nb][0]);
                    mma_bf16(c[mi][nb*2],   al[mi], &bh[nb][0]);
                    mma_bf16(c[mi][nb*2+1], ah[mi], &bh[nb][2]);
                    mma_bf16(c[mi][nb*2+1], ah[mi], &bl[nb][2]);
                    mma_bf16(c[mi][nb*2+1], al[mi], &bh[nb][2]);
                }
        }

        // atomicAdd epilogue
        const int lr0 = warp_m + (lane >> 2);
        const int col0 = dt * 128 + warp_n + (lane & 3) * 2;
        #pragma unroll
        for (int mi = 0; mi < 2; ++mi) {
            int r0 = lr0 + mi * 16;
            int r1 = r0 + 8;
            #pragma unroll
            for (int ni = 0; ni < 8; ++ni) {
                int col = col0 + ni * 8;
                if (t0 + r0 < n) {
                    float* p = out + (size_t)tok_s[r0] * DM + col;
                    atomicAdd(p,     c[mi][ni][0]);
                    atomicAdd(p + 1, c[mi][ni][1]);
                }
                if (t0 + r1 < n) {
                    float* p = out + (size_t)tok_s[r1] * DM + col;
                    atomicAdd(p,     c[mi][ni][2]);
                    atomicAdd(p + 1, c[mi][ni][3]);
                }
            }
        }
        __syncthreads();   // V smem reuse next dt
    }
}

extern "C" void kernel_launch(void* const* d_in, const int* in_sizes, int n_in,
                              void* d_out, int out_size)
{
    const float* x    = (const float*)d_in[0];
    const float* Wenc = (const float*)d_in[1];
    const float* benc = (const float*)d_in[2];
    const float* Wg   = (const float*)d_in[3];
    const float* U    = (const float*)d_in[4];
    const float* V    = (const float*)d_in[5];
    const float* gm   = (const float*)d_in[6];
    float* out = (float*)d_out;

    cudaFuncSetAttribute(encoder_mma,
                         cudaFuncAttributeMaxDynamicSharedMemorySize, ENC_SMEM);
    cudaFuncSetAttribute(expert_mma,
                         cudaFuncAttributeMaxDynamicSharedMemorySize, EXPM_SMEM);

    __nv_bfloat16 *xh, *xl, *wh, *wl, *uh, *ul, *vh, *vl;
    cudaGetSymbolAddress((void**)&xh, g_xh);
    cudaGetSymbolAddress((void**)&xl, g_xl);
    cudaGetSymbolAddress((void**)&wh, g_wh);
    cudaGetSymbolAddress((void**)&wl, g_wl);
    cudaGetSymbolAddress((void**)&uh, g_uh);
    cudaGetSymbolAddress((void**)&ul, g_ul);
    cudaGetSymbolAddress((void**)&vh, g_vh);
    cudaGetSymbolAddress((void**)&vl, g_vl);

    const int nx = B_TOK * DM, nw = DM * DM, nu = NEXP * RR * DM;
    split_bf16<<<(nx/4 + 255)/256, 256>>>(x, xh, xl, nx);
    split_bf16<<<(nw/4 + 255)/256, 256>>>(Wenc, wh, wl, nw);
    split_bf16<<<(nu/4 + 255)/256, 256>>>(U, uh, ul, nu);
    split_bf16<<<(nu/4 + 255)/256, 256>>>(V, vh, vl, nu);
    encoder_mma<<<dim3(DM/128, B_TOK/128), 256, ENC_SMEM>>>(benc, out);
    zero_counts<<<1, 32>>>();
    routing_kernel<<<B_TOK/16, 256>>>(Wg);
    expert_mma<<<dim3(B_TOK/128, NEXP), 256, EXPM_SMEM>>>(gm, out);
}

// round 9
// speedup vs baseline: 2.6180x; 1.1801x over previous
#include <cuda_runtime.h>
#include <cuda_fp16.h>
#include <cstdint>

// FlashMoE round 7: asymmetric precision.
//  - encoder: mma.sync fp16 hi/lo 3-term (W pre-scaled x64) -> enc err ~1e-7
//    (protects top-2 routing from tie flips). Writes out (fp32) + g_ef (fp16).
//  - experts: single-term fp16 mma (error ~2e-4 on delta, never affects routing).
//  - routing reads `out` (g_encoded removed).
// tcgen05 unavailable (harness PTX target compute_103).

#define B_TOK 16384
#define DM    2048
#define NEXP  16
#define RR    128
#define CAP   16384

__device__ int    g_cnt[NEXP];
__device__ int    g_tok[NEXP * CAP];
__device__ float  g_wgt[NEXP * CAP];
__device__ __half g_xh[(size_t)B_TOK * DM];
__device__ __half g_xl[(size_t)B_TOK * DM];
__device__ __half g_wh[(size_t)DM * DM];     // W_enc * 64, hi
__device__ __half g_wl[(size_t)DM * DM];     // W_enc * 64, lo
__device__ __half g_ef[(size_t)B_TOK * DM];  // fp16(encoded)
__device__ __half g_uf[(size_t)NEXP * RR * DM];
__device__ __half g_vf[(size_t)NEXP * DM * RR];

__device__ __forceinline__ uint32_t smem_u32(const void* p) {
    uint32_t a;
    asm("{ .reg .u64 t; cvta.to.shared.u64 t, %1; cvt.u32.u64 %0, t; }"
        : "=r"(a) : "l"(p));
    return a;
}
#define CP_ASYNC16(sm, gp) \
    asm volatile("cp.async.cg.shared.global [%0], [%1], 16;" :: "r"(sm), "l"(gp))
#define CP_COMMIT() asm volatile("cp.async.commit_group;" ::: "memory")
#define CP_WAIT1()  asm volatile("cp.async.wait_group 1;" ::: "memory")
#define CP_WAIT0()  asm volatile("cp.async.wait_group 0;" ::: "memory")

__device__ __forceinline__ void ldm_x4(uint32_t* r, uint32_t addr) {
    asm volatile("ldmatrix.sync.aligned.m8n8.x4.shared.b16 {%0,%1,%2,%3}, [%4];"
                 : "=r"(r[0]), "=r"(r[1]), "=r"(r[2]), "=r"(r[3]) : "r"(addr));
}
__device__ __forceinline__ void mma_f16(float* c, const uint32_t* a, const uint32_t* b) {
    asm volatile(
        "mma.sync.aligned.m16n8k16.row.col.f32.f16.f16.f32 "
        "{%0,%1,%2,%3}, {%4,%5,%6,%7}, {%8,%9}, {%0,%1,%2,%3};"
        : "+f"(c[0]), "+f"(c[1]), "+f"(c[2]), "+f"(c[3])
        : "r"(a[0]), "r"(a[1]), "r"(a[2]), "r"(a[3]), "r"(b[0]), "r"(b[1]));
}

// fp32 -> fp16 (hi, lo) split with pre-scale. n divisible by 4.
__global__ __launch_bounds__(256) void split_f16(
    const float* __restrict__ src, __half* __restrict__ hi,
    __half* __restrict__ lo, int n, float scale)
{
    int i = (blockIdx.x * blockDim.x + threadIdx.x) * 4;
    if (i >= n) return;
    float4 v = *(const float4*)(src + i);
    v.x *= scale; v.y *= scale; v.z *= scale; v.w *= scale;
    __half h0 = __float2half(v.x), h1 = __float2half(v.y);
    __half h2 = __float2half(v.z), h3 = __float2half(v.w);
    __half l0 = __float2half(v.x - __half2float(h0));
    __half l1 = __float2half(v.y - __half2float(h1));
    __half l2 = __float2half(v.z - __half2float(h2));
    __half l3 = __float2half(v.w - __half2float(h3));
    __half2* hp = (__half2*)(hi + i);
    __half2* lp = (__half2*)(lo + i);
    hp[0] = __half2(h0, h1); hp[1] = __half2(h2, h3);
    lp[0] = __half2(l0, l1); lp[1] = __half2(l2, l3);
}

// fp32 -> fp16 single
__global__ __launch_bounds__(256) void cvt_f16(
    const float* __restrict__ src, __half* __restrict__ dst, int n)
{
    int i = (blockIdx.x * blockDim.x + threadIdx.x) * 4;
    if (i >= n) return;
    float4 v = *(const float4*)(src + i);
    __half2* dp = (__half2*)(dst + i);
    dp[0] = __half2(__float2half(v.x), __float2half(v.y));
    dp[1] = __half2(__float2half(v.z), __float2half(v.w));
}

// ===========================================================================
// Encoder: 128x128 C-tile, BK=32 double-buffered cp.async, 8 warps (32m x 64n).
// fp16 3-term: ah*bh + ah*bl + al*bh (al*bl ~ 2^-24 dropped). B scaled x64,
// epilogue multiplies by 1/64. Smem rows 80B-strided -> conflict-free ldmatrix.
// ===========================================================================
#define BK        32
#define N_CHUNK   (DM / BK)        // 64
#define ROW_B     80
#define TILE_B    (128 * ROW_B)    // 10240
#define BUF_B     (4 * TILE_B)     // 40960
#define ENC_SMEM  (2 * BUF_B)      // 81920
#define INV64     0.015625f

__global__ __launch_bounds__(256, 2) void encoder_mma(
    const float* __restrict__ bias, float* __restrict__ out)
{
    extern __shared__ char smc[];
    const uint32_t sbase = smem_u32(smc);
    const int tid  = threadIdx.x;
    const int wid  = tid >> 5;
    const int lane = tid & 31;
    const int rowBase = blockIdx.y * 128;
    const int colBase = blockIdx.x * 128;
    const int warp_m = (wid & 3) * 32;
    const int warp_n = (wid >> 2) * 64;

    const int ldrow = tid >> 1;
    const int ldc0  = (tid & 1) * 2;
    const uint32_t srow_off = (uint32_t)(ldrow * ROW_B + ldc0 * 16);

    const __half* gah = g_xh + (size_t)(rowBase + ldrow) * DM + ldc0 * 8;
    const __half* gal = g_xl + (size_t)(rowBase + ldrow) * DM + ldc0 * 8;
    const __half* gbh = g_wh + (size_t)(colBase + ldrow) * DM + ldc0 * 8;
    const __half* gbl = g_wl + (size_t)(colBase + ldrow) * DM + ldc0 * 8;

    float c[2][8][4];
    #pragma unroll
    for (int mi = 0; mi < 2; ++mi)
        #pragma unroll
        for (int ni = 0; ni < 8; ++ni)
            #pragma unroll
            for (int q = 0; q < 4; ++q) c[mi][ni][q] = 0.f;

    const int a_r = lane & 15;
    const int a_k = (lane >> 4) * 8;
    const int b_r = ((lane >> 4) << 3) + (lane & 7);
    const int b_k = ((lane >> 3) & 1) * 8;

    auto issue_loads = [&](int chunk, int buf) {
        const uint32_t s0 = sbase + buf * BUF_B + srow_off;
        const size_t gofs = (size_t)chunk * BK;
        CP_ASYNC16(s0 + 0 * TILE_B,      gah + gofs);
        CP_ASYNC16(s0 + 0 * TILE_B + 16, gah + gofs + 8);
        CP_ASYNC16(s0 + 1 * TILE_B,      gal + gofs);
        CP_ASYNC16(s0 + 1 * TILE_B + 16, gal + gofs + 8);
        CP_ASYNC16(s0 + 2 * TILE_B,      gbh + gofs);
        CP_ASYNC16(s0 + 2 * TILE_B + 16, gbh + gofs + 8);
        CP_ASYNC16(s0 + 3 * TILE_B,      gbl + gofs);
        CP_ASYNC16(s0 + 3 * TILE_B + 16, gbl + gofs + 8);
        CP_COMMIT();
    };

    issue_loads(0, 0);

    for (int chunk = 0; chunk < N_CHUNK; ++chunk) {
        const int buf = chunk & 1;
        if (chunk + 1 < N_CHUNK) { issue_loads(chunk + 1, buf ^ 1); CP_WAIT1(); }
        else                     { CP_WAIT0(); }
        __syncthreads();

        const uint32_t tb = sbase + buf * BUF_B;
        #pragma unroll
        for (int ks = 0; ks < 2; ++ks) {
            uint32_t ah[2][4], al[2][4], bh[4][4], bl[4][4];
            #pragma unroll
            for (int mi = 0; mi < 2; ++mi) {
                uint32_t ao = (uint32_t)((warp_m + mi * 16 + a_r) * ROW_B
                                         + (ks * 16 + a_k) * 2);
                ldm_x4(ah[mi], tb + 0 * TILE_B + ao);
                ldm_x4(al[mi], tb + 1 * TILE_B + ao);
            }
            #pragma unroll
            for (int nb = 0; nb < 4; ++nb) {
                uint32_t bo = (uint32_t)((warp_n + nb * 16 + b_r) * ROW_B
                                         + (ks * 16 + b_k) * 2);
                ldm_x4(bh[nb], tb + 2 * TILE_B + bo);
                ldm_x4(bl[nb], tb + 3 * TILE_B + bo);
            }
            #pragma unroll
            for (int mi = 0; mi < 2; ++mi)
                #pragma unroll
                for (int nb = 0; nb < 4; ++nb) {
                    mma_f16(c[mi][nb*2],   ah[mi], &bh[nb][0]);
                    mma_f16(c[mi][nb*2],   ah[mi], &bl[nb][0]);
                    mma_f16(c[mi][nb*2],   al[mi], &bh[nb][0]);
                    mma_f16(c[mi][nb*2+1], ah[mi], &bh[nb][2]);
                    mma_f16(c[mi][nb*2+1], ah[mi], &bl[nb][2]);
                    mma_f16(c[mi][nb*2+1], al[mi], &bh[nb][2]);
                }
        }
        __syncthreads();
    }

    // epilogue: c/64 + bias; store fp32 to out, fp16 to g_ef
    const int erow = rowBase + warp_m + (lane >> 2);
    const int ecol0 = colBase + warp_n + (lane & 3) * 2;
    #pragma unroll
    for (int mi = 0; mi < 2; ++mi) {
        #pragma unroll
        for (int ni = 0; ni < 8; ++ni) {
            int col = ecol0 + ni * 8;
            float b0 = bias[col], b1 = bias[col + 1];
            int r0 = erow + mi * 16;
            float v00 = c[mi][ni][0] * INV64 + b0, v01 = c[mi][ni][1] * INV64 + b1;
            float v10 = c[mi][ni][2] * INV64 + b0, v11 = c[mi][ni][3] * INV64 + b1;
            size_t o0 = (size_t)r0 * DM + col;
            size_t o1 = (size_t)(r0 + 8) * DM + col;
            *(float2*)(out + o0) = make_float2(v00, v01);
            *(float2*)(out + o1) = make_float2(v10, v11);
            *(__half2*)(g_ef + o0) = __half2(__float2half(v00), __float2half(v01));
            *(__half2*)(g_ef + o1) = __half2(__float2half(v10), __float2half(v11));
        }
    }
}

__global__ void zero_counts()
{
    if (threadIdx.x < NEXP) g_cnt[threadIdx.x] = 0;
}

// Routing: one warp / 2 tokens; reads fp32 enc from `out`. Top-2, 2-way softmax.
__global__ __launch_bounds__(256) void routing_kernel(
    const float* __restrict__ enc, const float* __restrict__ Wg)
{
    const int warp = (blockIdx.x * blockDim.x + threadIdx.x) >> 5;
    const int lane = threadIdx.x & 31;
    const int b0 = warp * 2;
    if (b0 >= B_TOK) return;

    const float4* x0 = (const float4*)(enc + (size_t)b0 * DM);
    const float4* x1 = (const float4*)(enc + (size_t)(b0 + 1) * DM);
    const float4* wg = (const float4*)Wg;

    float a0[NEXP], a1[NEXP];
    #pragma unroll
    for (int m = 0; m < NEXP; ++m) { a0[m] = 0.f; a1[m] = 0.f; }

    for (int it = 0; it < DM / 128; ++it) {
        int d4 = it * 32 + lane;
        float4 v0 = x0[d4];
        float4 v1 = x1[d4];
        #pragma unroll
        for (int m = 0; m < NEXP; ++m) {
            float4 w = wg[m * (DM / 4) + d4];
            a0[m] += v0.x*w.x + v0.y*w.y + v0.z*w.z + v0.w*w.w;
            a1[m] += v1.x*w.x + v1.y*w.y + v1.z*w.z + v1.w*w.w;
        }
    }
    #pragma unroll
    for (int m = 0; m < NEXP; ++m) {
        #pragma unroll
        for (int off = 16; off > 0; off >>= 1) {
            a0[m] += __shfl_xor_sync(0xffffffffu, a0[m], off);
            a1[m] += __shfl_xor_sync(0xffffffffu, a1[m], off);
        }
    }
    if (lane < 2) {
        float v[NEXP];
        #pragma unroll
        for (int m = 0; m < NEXP; ++m) v[m] = (lane == 0) ? a0[m] : a1[m];
        const int b = b0 + lane;

        float best = v[0]; int bi = 0;
        #pragma unroll
        for (int m = 1; m < NEXP; ++m)
            if (v[m] > best) { best = v[m]; bi = m; }
        float best2 = -3.402823466e38f; int bi2 = 0;
        #pragma unroll
        for (int m = 0; m < NEXP; ++m)
            if (m != bi && v[m] > best2) { best2 = v[m]; bi2 = m; }

        float e2 = __expf(best2 - best);
        float denom = 1.f + e2 + 1e-12f;
        float w1 = 1.f / denom;
        float w2 = e2 / denom;
        if (w1 > 1e-12f) {
            int p = atomicAdd(&g_cnt[bi], 1);
            g_tok[bi * CAP + p] = b; g_wgt[bi * CAP + p] = w1;
        }
        if (w2 > 1e-12f) {
            int p = atomicAdd(&g_cnt[bi2], 1);
            g_tok[bi2 * CAP + p] = b; g_wgt[bi2 * CAP + p] = w2;
        }
    }
}

// ===========================================================================
// Expert kernel, single-term fp16. Block 256 thr, grid (128 tiles, 16 experts).
// Phase1: S = silu(gather(g_ef) @ uf^T)*cw, K=2048, double-buffered (A,U tiles).
// Phase2: per d-tile: C = S @ vf_tile^T, K=128, V double-buffered; atomicAdd.
// Smem: phase1 2 bufs x (A 10240 + U 10240) = 40960;
//       phase2 S @0 (34816, overlaps dead phase1 bufs) + V bufs @34816 (2x34816).
// ===========================================================================
#define ROW2_B    272
#define S_OFF     0
#define V_OFF     34816
#define EXPF_SMEM (V_OFF + 2 * 34816)   // 104448

__global__ __launch_bounds__(256, 2) void expert_f16(
    const float* __restrict__ gamma, float* __restrict__ out)
{
    const int e = blockIdx.y;
    const int n = g_cnt[e];
    const int t0 = blockIdx.x * 128;
    if (t0 >= n) return;

    extern __shared__ char smc[];
    const uint32_t sbase = smem_u32(smc);
    __shared__ int   tok_s[128];
    __shared__ float cw_s[128];

    const int tid  = threadIdx.x;
    const int wid  = tid >> 5;
    const int lane = tid & 31;
    if (tid < 128) {
        int idx = t0 + tid;
        if (idx < n) {
            tok_s[tid] = g_tok[e * CAP + idx];
            cw_s[tid]  = g_wgt[e * CAP + idx] * gamma[e];
        } else {
            tok_s[tid] = 0;
            cw_s[tid]  = 0.f;
        }
    }
    __syncthreads();

    const int warp_m = (wid & 3) * 32;
    const int warp_n = (wid >> 2) * 64;
    const int a_r = lane & 15;
    const int a_k = (lane >> 4) * 8;
    const int b_r = ((lane >> 4) << 3) + (lane & 7);
    const int b_k = ((lane >> 3) & 1) * 8;

    // ---------------- Phase 1: up-projection (K = 2048), single-term --------
    {
        const int ldrow = tid >> 1;
        const int ldc0  = (tid & 1) * 2;
        const uint32_t srow_off = (uint32_t)(ldrow * ROW_B + ldc0 * 16);
        const __half* ga = g_ef + (size_t)tok_s[ldrow] * DM + ldc0 * 8;
        const __half* gb = g_uf + (size_t)e * RR * DM + (size_t)ldrow * DM + ldc0 * 8;

        float c[2][8][4];
        #pragma unroll
        for (int mi = 0; mi < 2; ++mi)
            #pragma unroll
            for (int ni = 0; ni < 8; ++ni)
                #pragma unroll
                for (int q = 0; q < 4; ++q) c[mi][ni][q] = 0.f;

        auto issue_loads = [&](int chunk, int buf) {
            const uint32_t s0 = sbase + buf * (2 * TILE_B) + srow_off;
            const size_t gofs = (size_t)chunk * BK;
            CP_ASYNC16(s0,               ga + gofs);
            CP_ASYNC16(s0 + 16,          ga + gofs + 8);
            CP_ASYNC16(s0 + TILE_B,      gb + gofs);
            CP_ASYNC16(s0 + TILE_B + 16, gb + gofs + 8);
            CP_COMMIT();
        };

        issue_loads(0, 0);
        for (int chunk = 0; chunk < N_CHUNK; ++chunk) {
            const int buf = chunk & 1;
            if (chunk + 1 < N_CHUNK) { issue_loads(chunk + 1, buf ^ 1); CP_WAIT1(); }
            else                     { CP_WAIT0(); }
            __syncthreads();

            const uint32_t tb = sbase + buf * (2 * TILE_B);
            #pragma unroll
            for (int ks = 0; ks < 2; ++ks) {
                uint32_t af[2][4], bf[4][4];
                #pragma unroll
                for (int mi = 0; mi < 2; ++mi) {
                    uint32_t ao = (uint32_t)((warp_m + mi * 16 + a_r) * ROW_B
                                             + (ks * 16 + a_k) * 2);
                    ldm_x4(af[mi], tb + ao);
                }
                #pragma unroll
                for (int nb = 0; nb < 4; ++nb) {
                    uint32_t bo = (uint32_t)((warp_n + nb * 16 + b_r) * ROW_B
                                             + (ks * 16 + b_k) * 2);
                    ldm_x4(bf[nb], tb + TILE_B + bo);
                }
                #pragma unroll
                for (int mi = 0; mi < 2; ++mi)
                    #pragma unroll
                    for (int nb = 0; nb < 4; ++nb) {
                        mma_f16(c[mi][nb*2],   af[mi], &bf[nb][0]);
                        mma_f16(c[mi][nb*2+1], af[mi], &bf[nb][2]);
                    }
            }
            __syncthreads();
        }

        // silu * cw -> S (fp16) in smem. Rows = tokens, cols = r.
        const int er  = warp_m + (lane >> 2);
        const int ec0 = warp_n + (lane & 3) * 2;
        #pragma unroll
        for (int mi = 0; mi < 2; ++mi) {
            int r0 = er + mi * 16;
            int r1 = r0 + 8;
            float w0 = cw_s[r0], w1 = cw_s[r1];
            #pragma unroll
            for (int ni = 0; ni < 8; ++ni) {
                int col = ec0 + ni * 8;
                float x00 = c[mi][ni][0], x01 = c[mi][ni][1];
                float x10 = c[mi][ni][2], x11 = c[mi][ni][3];
                float v00 = x00 / (1.f + __expf(-x00)) * w0;
                float v01 = x01 / (1.f + __expf(-x01)) * w0;
                float v10 = x10 / (1.f + __expf(-x10)) * w1;
                float v11 = x11 / (1.f + __expf(-x11)) * w1;
                *(__half2*)(smc + S_OFF + r0 * ROW2_B + col * 2) =
                    __half2(__float2half(v00), __float2half(v01));
                *(__half2*)(smc + S_OFF + r1 * ROW2_B + col * 2) =
                    __half2(__float2half(v10), __float2half(v11));
            }
        }
    }
    __syncthreads();

    // ---------------- Phase 2: down-projection, 16 d-tiles (K = 128) --------
    const int vrow = tid >> 1;
    const int vc0  = (tid & 1) * 8;
    const __half* gv = g_vf + (size_t)e * DM * RR + (size_t)vrow * RR + vc0 * 8;

    auto issue_v = [&](int dt, int buf) {
        const uint32_t s0 = sbase + V_OFF + buf * 34816
                          + (uint32_t)(vrow * ROW2_B + vc0 * 16);
        const __half* g = gv + (size_t)dt * 128 * RR;
        #pragma unroll
        for (int i = 0; i < 8; ++i)
            CP_ASYNC16(s0 + i * 16, g + i * 8);
        CP_COMMIT();
    };

    issue_v(0, 0);
    for (int dt = 0; dt < 16; ++dt) {
        const int buf = dt & 1;
        if (dt + 1 < 16) { issue_v(dt + 1, buf ^ 1); CP_WAIT1(); }
        else             { CP_WAIT0(); }
        __syncthreads();

        const uint32_t vb = sbase + V_OFF + buf * 34816;
        float c[2][8][4];
        #pragma unroll
        for (int mi = 0; mi < 2; ++mi)
            #pragma unroll
            for (int ni = 0; ni < 8; ++ni)
                #pragma unroll
                for (int q = 0; q < 4; ++q) c[mi][ni][q] = 0.f;

        #pragma unroll
        for (int ks = 0; ks < 8; ++ks) {
            uint32_t af[2][4], bf[4][4];
            #pragma unroll
            for (int mi = 0; mi < 2; ++mi) {
                uint32_t ao = (uint32_t)((warp_m + mi * 16 + a_r) * ROW2_B
                                         + (ks * 16 + a_k) * 2);
                ldm_x4(af[mi], sbase + S_OFF + ao);
            }
            #pragma unroll
            for (int nb = 0; nb < 4; ++nb) {
                uint32_t bo = (uint32_t)((warp_n + nb * 16 + b_r) * ROW2_B
                                         + (ks * 16 + b_k) * 2);
                ldm_x4(bf[nb], vb + bo);
            }
            #pragma unroll
            for (int mi = 0; mi < 2; ++mi)
                #pragma unroll
                for (int nb = 0; nb < 4; ++nb) {
                    mma_f16(c[mi][nb*2],   af[mi], &bf[nb][0]);
                    mma_f16(c[mi][nb*2+1], af[mi], &bf[nb][2]);
                }
        }

        const int lr0 = warp_m + (lane >> 2);
        const int col0 = dt * 128 + warp_n + (lane & 3) * 2;
        #pragma unroll
        for (int mi = 0; mi < 2; ++mi) {
            int r0 = lr0 + mi * 16;
            int r1 = r0 + 8;
            #pragma unroll
            for (int ni = 0; ni < 8; ++ni) {
                int col = col0 + ni * 8;
                if (t0 + r0 < n) {
                    float* p = out + (size_t)tok_s[r0] * DM + col;
                    atomicAdd(p,     c[mi][ni][0]);
                    atomicAdd(p + 1, c[mi][ni][1]);
                }
                if (t0 + r1 < n) {
                    float* p = out + (size_t)tok_s[r1] * DM + col;
                    atomicAdd(p,     c[mi][ni][2]);
                    atomicAdd(p + 1, c[mi][ni][3]);
                }
            }
        }
        __syncthreads();
    }
}

extern "C" void kernel_launch(void* const* d_in, const int* in_sizes, int n_in,
                              void* d_out, int out_size)
{
    const float* x    = (const float*)d_in[0];
    const float* Wenc = (const float*)d_in[1];
    const float* benc = (const float*)d_in[2];
    const float* Wg   = (const float*)d_in[3];
    const float* U    = (const float*)d_in[4];
    const float* V    = (const float*)d_in[5];
    const float* gm   = (const float*)d_in[6];
    float* out = (float*)d_out;

    cudaFuncSetAttribute(encoder_mma,
                         cudaFuncAttributeMaxDynamicSharedMemorySize, ENC_SMEM);
    cudaFuncSetAttribute(expert_f16,
                         cudaFuncAttributeMaxDynamicSharedMemorySize, EXPF_SMEM);

    __half *xh, *xl, *wh, *wl, *uf, *vf;
    cudaGetSymbolAddress((void**)&xh, g_xh);
    cudaGetSymbolAddress((void**)&xl, g_xl);
    cudaGetSymbolAddress((void**)&wh, g_wh);
    cudaGetSymbolAddress((void**)&wl, g_wl);
    cudaGetSymbolAddress((void**)&uf, g_uf);
    cudaGetSymbolAddress((void**)&vf, g_vf);

    const int nx = B_TOK * DM, nw = DM * DM, nu = NEXP * RR * DM;
    split_f16<<<(nx/4 + 255)/256, 256>>>(x, xh, xl, nx, 1.0f);
    split_f16<<<(nw/4 + 255)/256, 256>>>(Wenc, wh, wl, nw, 64.0f);
    cvt_f16<<<(nu/4 + 255)/256, 256>>>(U, uf, nu);
    cvt_f16<<<(nu/4 + 255)/256, 256>>>(V, vf, nu);
    encoder_mma<<<dim3(DM/128, B_TOK/128), 256, ENC_SMEM>>>(benc, out);
    zero_counts<<<1, 32>>>();
    routing_kernel<<<B_TOK/16, 256>>>(out, Wg);
    expert_f16<<<dim3(B_TOK/128, NEXP), 256, EXPF_SMEM>>>(gm, out);
}

// round 10
// speedup vs baseline: 3.0447x; 1.1630x over previous
#include <cuda_runtime.h>
#include <cuda_fp16.h>
#include <cstdint>

// FlashMoE round 10: exact routing via Weff = Wg@W_enc (fp32, from x directly),
// which decouples routing correctness from encoder precision. Encoder drops to
// single-term fp16 mma (3x fewer HMMA). Experts single-term fp16 (unchanged).
// tcgen05 unavailable (harness PTX target compute_103).
//
// Pipeline:
//   0) cvt_f16 x4: x, W_enc, U, V -> fp16
//   1) weff_kernel: Weff[16,2048] = Wg@W_enc, bg[16] = Wg@b   (fp32, exact)
//   2) zero_counts; routing_kernel: logits = x@Weff^T + bg, top-2, scatter
//   3) encoder_mma: enc = x@W_enc^T + b (fp16 single-term) -> out fp32 + g_ef fp16
//   4) expert_f16: S = silu(gather(g_ef)@U^T)*w*gamma; delta = S@V^T; atomicAdd

#define B_TOK 16384
#define DM    2048
#define NEXP  16
#define RR    128
#define CAP   16384

__device__ int    g_cnt[NEXP];
__device__ int    g_tok[NEXP * CAP];
__device__ float  g_wgt[NEXP * CAP];
__device__ float  g_weff[NEXP * DM];
__device__ float  g_bg[NEXP];
__device__ __half g_xf[(size_t)B_TOK * DM];
__device__ __half g_wf[(size_t)DM * DM];
__device__ __half g_ef[(size_t)B_TOK * DM];
__device__ __half g_uf[(size_t)NEXP * RR * DM];
__device__ __half g_vf[(size_t)NEXP * DM * RR];

__device__ __forceinline__ uint32_t smem_u32(const void* p) {
    uint32_t a;
    asm("{ .reg .u64 t; cvta.to.shared.u64 t, %1; cvt.u32.u64 %0, t; }"
        : "=r"(a) : "l"(p));
    return a;
}
#define CP_ASYNC16(sm, gp) \
    asm volatile("cp.async.cg.shared.global [%0], [%1], 16;" :: "r"(sm), "l"(gp))
#define CP_COMMIT() asm volatile("cp.async.commit_group;" ::: "memory")
#define CP_WAIT1()  asm volatile("cp.async.wait_group 1;" ::: "memory")
#define CP_WAIT0()  asm volatile("cp.async.wait_group 0;" ::: "memory")

__device__ __forceinline__ void ldm_x4(uint32_t* r, uint32_t addr) {
    asm volatile("ldmatrix.sync.aligned.m8n8.x4.shared.b16 {%0,%1,%2,%3}, [%4];"
                 : "=r"(r[0]), "=r"(r[1]), "=r"(r[2]), "=r"(r[3]) : "r"(addr));
}
__device__ __forceinline__ void mma_f16(float* c, const uint32_t* a, const uint32_t* b) {
    asm volatile(
        "mma.sync.aligned.m16n8k16.row.col.f32.f16.f16.f32 "
        "{%0,%1,%2,%3}, {%4,%5,%6,%7}, {%8,%9}, {%0,%1,%2,%3};"
        : "+f"(c[0]), "+f"(c[1]), "+f"(c[2]), "+f"(c[3])
        : "r"(a[0]), "r"(a[1]), "r"(a[2]), "r"(a[3]), "r"(b[0]), "r"(b[1]));
}

__global__ __launch_bounds__(256) void cvt_f16(
    const float* __restrict__ src, __half* __restrict__ dst, int n)
{
    int i = (blockIdx.x * blockDim.x + threadIdx.x) * 4;
    if (i >= n) return;
    float4 v = *(const float4*)(src + i);
    __half2* dp = (__half2*)(dst + i);
    dp[0] = __half2(__float2half(v.x), __float2half(v.y));
    dp[1] = __half2(__float2half(v.z), __float2half(v.w));
}

// ===========================================================================
// Weff = Wg @ W_enc  ([16,2048] = [16,2048]x[2048,2048]); bg = Wg @ b.
// Grid 8 x 256 threads: thread owns output column k; W_enc column reads are
// coalesced across threads. Wg chunk cached in smem.
// ===========================================================================
__global__ __launch_bounds__(256) void weff_kernel(
    const float* __restrict__ Wg, const float* __restrict__ Wenc,
    const float* __restrict__ b)
{
    __shared__ float wg_s[NEXP][128];
    const int tid = threadIdx.x;
    const int k = blockIdx.x * 256 + tid;

    float acc[NEXP];
    #pragma unroll
    for (int m = 0; m < NEXP; ++m) acc[m] = 0.f;

    for (int jc = 0; jc < DM; jc += 128) {
        for (int t = tid; t < NEXP * 128; t += 256)
            wg_s[t >> 7][t & 127] = Wg[(t >> 7) * DM + jc + (t & 127)];
        __syncthreads();
        for (int j = 0; j < 128; ++j) {
            float w = Wenc[(size_t)(jc + j) * DM + k];
            #pragma unroll
            for (int m = 0; m < NEXP; ++m) acc[m] += wg_s[m][j] * w;
        }
        __syncthreads();
    }
    #pragma unroll
    for (int m = 0; m < NEXP; ++m) g_weff[m * DM + k] = acc[m];

    if (blockIdx.x == 0 && tid < NEXP) {
        float s = 0.f;
        for (int j = 0; j < DM; ++j) s += Wg[tid * DM + j] * b[j];
        g_bg[tid] = s;
    }
}

__global__ void zero_counts()
{
    if (threadIdx.x < NEXP) g_cnt[threadIdx.x] = 0;
}

// Routing from x + Weff (exact fp32, independent of encoder precision).
__global__ __launch_bounds__(256) void routing_kernel(
    const float* __restrict__ x)
{
    const int warp = (blockIdx.x * blockDim.x + threadIdx.x) >> 5;
    const int lane = threadIdx.x & 31;
    const int b0 = warp * 2;
    if (b0 >= B_TOK) return;

    const float4* x0 = (const float4*)(x + (size_t)b0 * DM);
    const float4* x1 = (const float4*)(x + (size_t)(b0 + 1) * DM);
    const float4* wg = (const float4*)g_weff;

    float a0[NEXP], a1[NEXP];
    #pragma unroll
    for (int m = 0; m < NEXP; ++m) { a0[m] = 0.f; a1[m] = 0.f; }

    for (int it = 0; it < DM / 128; ++it) {
        int d4 = it * 32 + lane;
        float4 v0 = x0[d4];
        float4 v1 = x1[d4];
        #pragma unroll
        for (int m = 0; m < NEXP; ++m) {
            float4 w = wg[m * (DM / 4) + d4];
            a0[m] += v0.x*w.x + v0.y*w.y + v0.z*w.z + v0.w*w.w;
            a1[m] += v1.x*w.x + v1.y*w.y + v1.z*w.z + v1.w*w.w;
        }
    }
    #pragma unroll
    for (int m = 0; m < NEXP; ++m) {
        #pragma unroll
        for (int off = 16; off > 0; off >>= 1) {
            a0[m] += __shfl_xor_sync(0xffffffffu, a0[m], off);
            a1[m] += __shfl_xor_sync(0xffffffffu, a1[m], off);
        }
    }
    if (lane < 2) {
        float v[NEXP];
        #pragma unroll
        for (int m = 0; m < NEXP; ++m)
            v[m] = ((lane == 0) ? a0[m] : a1[m]) + g_bg[m];
        const int b = b0 + lane;

        float best = v[0]; int bi = 0;
        #pragma unroll
        for (int m = 1; m < NEXP; ++m)
            if (v[m] > best) { best = v[m]; bi = m; }
        float best2 = -3.402823466e38f; int bi2 = 0;
        #pragma unroll
        for (int m = 0; m < NEXP; ++m)
            if (m != bi && v[m] > best2) { best2 = v[m]; bi2 = m; }

        float e2 = __expf(best2 - best);
        float denom = 1.f + e2 + 1e-12f;
        float w1 = 1.f / denom;
        float w2 = e2 / denom;
        if (w1 > 1e-12f) {
            int p = atomicAdd(&g_cnt[bi], 1);
            g_tok[bi * CAP + p] = b; g_wgt[bi * CAP + p] = w1;
        }
        if (w2 > 1e-12f) {
            int p = atomicAdd(&g_cnt[bi2], 1);
            g_tok[bi2 * CAP + p] = b; g_wgt[bi2 * CAP + p] = w2;
        }
    }
}

// ===========================================================================
// Encoder: 128x128 C-tile, BK=32 double-buffered cp.async, 8 warps (32m x 64n),
// single-term fp16 (routing no longer depends on enc precision).
// Smem rows 80B-strided -> conflict-free ldmatrix.
// ===========================================================================
#define BK        32
#define N_CHUNK   (DM / BK)        // 64
#define ROW_B     80
#define TILE_B    (128 * ROW_B)    // 10240
#define ENC_SMEM  (2 * 2 * TILE_B) // 40960 (2 bufs x (A,B))

__global__ __launch_bounds__(256, 2) void encoder_mma(
    const float* __restrict__ bias, float* __restrict__ out)
{
    extern __shared__ char smc[];
    const uint32_t sbase = smem_u32(smc);
    const int tid  = threadIdx.x;
    const int wid  = tid >> 5;
    const int lane = tid & 31;
    const int rowBase = blockIdx.y * 128;
    const int colBase = blockIdx.x * 128;
    const int warp_m = (wid & 3) * 32;
    const int warp_n = (wid >> 2) * 64;

    const int ldrow = tid >> 1;
    const int ldc0  = (tid & 1) * 2;
    const uint32_t srow_off = (uint32_t)(ldrow * ROW_B + ldc0 * 16);

    const __half* ga = g_xf + (size_t)(rowBase + ldrow) * DM + ldc0 * 8;
    const __half* gb = g_wf + (size_t)(colBase + ldrow) * DM + ldc0 * 8;

    float c[2][8][4];
    #pragma unroll
    for (int mi = 0; mi < 2; ++mi)
        #pragma unroll
        for (int ni = 0; ni < 8; ++ni)
            #pragma unroll
            for (int q = 0; q < 4; ++q) c[mi][ni][q] = 0.f;

    const int a_r = lane & 15;
    const int a_k = (lane >> 4) * 8;
    const int b_r = ((lane >> 4) << 3) + (lane & 7);
    const int b_k = ((lane >> 3) & 1) * 8;

    auto issue_loads = [&](int chunk, int buf) {
        const uint32_t s0 = sbase + buf * (2 * TILE_B) + srow_off;
        const size_t gofs = (size_t)chunk * BK;
        CP_ASYNC16(s0,               ga + gofs);
        CP_ASYNC16(s0 + 16,          ga + gofs + 8);
        CP_ASYNC16(s0 + TILE_B,      gb + gofs);
        CP_ASYNC16(s0 + TILE_B + 16, gb + gofs + 8);
        CP_COMMIT();
    };

    issue_loads(0, 0);

    for (int chunk = 0; chunk < N_CHUNK; ++chunk) {
        const int buf = chunk & 1;
        if (chunk + 1 < N_CHUNK) { issue_loads(chunk + 1, buf ^ 1); CP_WAIT1(); }
        else                     { CP_WAIT0(); }
        __syncthreads();

        const uint32_t tb = sbase + buf * (2 * TILE_B);
        #pragma unroll
        for (int ks = 0; ks < 2; ++ks) {
            uint32_t af[2][4], bf[4][4];
            #pragma unroll
            for (int mi = 0; mi < 2; ++mi) {
                uint32_t ao = (uint32_t)((warp_m + mi * 16 + a_r) * ROW_B
                                         + (ks * 16 + a_k) * 2);
                ldm_x4(af[mi], tb + ao);
            }
            #pragma unroll
            for (int nb = 0; nb < 4; ++nb) {
                uint32_t bo = (uint32_t)((warp_n + nb * 16 + b_r) * ROW_B
                                         + (ks * 16 + b_k) * 2);
                ldm_x4(bf[nb], tb + TILE_B + bo);
            }
            #pragma unroll
            for (int mi = 0; mi < 2; ++mi)
                #pragma unroll
                for (int nb = 0; nb < 4; ++nb) {
                    mma_f16(c[mi][nb*2],   af[mi], &bf[nb][0]);
                    mma_f16(c[mi][nb*2+1], af[mi], &bf[nb][2]);
                }
        }
        __syncthreads();
    }

    // epilogue: + bias; store fp32 to out, fp16 to g_ef
    const int erow = rowBase + warp_m + (lane >> 2);
    const int ecol0 = colBase + warp_n + (lane & 3) * 2;
    #pragma unroll
    for (int mi = 0; mi < 2; ++mi) {
        #pragma unroll
        for (int ni = 0; ni < 8; ++ni) {
            int col = ecol0 + ni * 8;
            float b0 = bias[col], b1 = bias[col + 1];
            int r0 = erow + mi * 16;
            float v00 = c[mi][ni][0] + b0, v01 = c[mi][ni][1] + b1;
            float v10 = c[mi][ni][2] + b0, v11 = c[mi][ni][3] + b1;
            size_t o0 = (size_t)r0 * DM + col;
            size_t o1 = (size_t)(r0 + 8) * DM + col;
            *(float2*)(out + o0) = make_float2(v00, v01);
            *(float2*)(out + o1) = make_float2(v10, v11);
            *(__half2*)(g_ef + o0) = __half2(__float2half(v00), __float2half(v01));
            *(__half2*)(g_ef + o1) = __half2(__float2half(v10), __float2half(v11));
        }
    }
}

// ===========================================================================
// Expert kernel, single-term fp16 (unchanged from round 9, passing).
// ===========================================================================
#define ROW2_B    272
#define S_OFF     0
#define V_OFF     34816
#define EXPF_SMEM (V_OFF + 2 * 34816)   // 104448

__global__ __launch_bounds__(256, 2) void expert_f16(
    const float* __restrict__ gamma, float* __restrict__ out)
{
    const int e = blockIdx.y;
    const int n = g_cnt[e];
    const int t0 = blockIdx.x * 128;
    if (t0 >= n) return;

    extern __shared__ char smc[];
    const uint32_t sbase = smem_u32(smc);
    __shared__ int   tok_s[128];
    __shared__ float cw_s[128];

    const int tid  = threadIdx.x;
    const int wid  = tid >> 5;
    const int lane = tid & 31;
    if (tid < 128) {
        int idx = t0 + tid;
        if (idx < n) {
            tok_s[tid] = g_tok[e * CAP + idx];
            cw_s[tid]  = g_wgt[e * CAP + idx] * gamma[e];
        } else {
            tok_s[tid] = 0;
            cw_s[tid]  = 0.f;
        }
    }
    __syncthreads();

    const int warp_m = (wid & 3) * 32;
    const int warp_n = (wid >> 2) * 64;
    const int a_r = lane & 15;
    const int a_k = (lane >> 4) * 8;
    const int b_r = ((lane >> 4) << 3) + (lane & 7);
    const int b_k = ((lane >> 3) & 1) * 8;

    // ---------------- Phase 1: up-projection (K = 2048) ----------------
    {
        const int ldrow = tid >> 1;
        const int ldc0  = (tid & 1) * 2;
        const uint32_t srow_off = (uint32_t)(ldrow * ROW_B + ldc0 * 16);
        const __half* ga = g_ef + (size_t)tok_s[ldrow] * DM + ldc0 * 8;
        const __half* gb = g_uf + (size_t)e * RR * DM + (size_t)ldrow * DM + ldc0 * 8;

        float c[2][8][4];
        #pragma unroll
        for (int mi = 0; mi < 2; ++mi)
            #pragma unroll
            for (int ni = 0; ni < 8; ++ni)
                #pragma unroll
                for (int q = 0; q < 4; ++q) c[mi][ni][q] = 0.f;

        auto issue_loads = [&](int chunk, int buf) {
            const uint32_t s0 = sbase + buf * (2 * TILE_B) + srow_off;
            const size_t gofs = (size_t)chunk * BK;
            CP_ASYNC16(s0,               ga + gofs);
            CP_ASYNC16(s0 + 16,          ga + gofs + 8);
            CP_ASYNC16(s0 + TILE_B,      gb + gofs);
            CP_ASYNC16(s0 + TILE_B + 16, gb + gofs + 8);
            CP_COMMIT();
        };

        issue_loads(0, 0);
        for (int chunk = 0; chunk < N_CHUNK; ++chunk) {
            const int buf = chunk & 1;
            if (chunk + 1 < N_CHUNK) { issue_loads(chunk + 1, buf ^ 1); CP_WAIT1(); }
            else                     { CP_WAIT0(); }
            __syncthreads();

            const uint32_t tb = sbase + buf * (2 * TILE_B);
            #pragma unroll
            for (int ks = 0; ks < 2; ++ks) {
                uint32_t af[2][4], bf[4][4];
                #pragma unroll
                for (int mi = 0; mi < 2; ++mi) {
                    uint32_t ao = (uint32_t)((warp_m + mi * 16 + a_r) * ROW_B
                                             + (ks * 16 + a_k) * 2);
                    ldm_x4(af[mi], tb + ao);
                }
                #pragma unroll
                for (int nb = 0; nb < 4; ++nb) {
                    uint32_t bo = (uint32_t)((warp_n + nb * 16 + b_r) * ROW_B
                                             + (ks * 16 + b_k) * 2);
                    ldm_x4(bf[nb], tb + TILE_B + bo);
                }
                #pragma unroll
                for (int mi = 0; mi < 2; ++mi)
                    #pragma unroll
                    for (int nb = 0; nb < 4; ++nb) {
                        mma_f16(c[mi][nb*2],   af[mi], &bf[nb][0]);
                        mma_f16(c[mi][nb*2+1], af[mi], &bf[nb][2]);
                    }
            }
            __syncthreads();
        }

        // silu * cw -> S (fp16) in smem
        const int er  = warp_m + (lane >> 2);
        const int ec0 = warp_n + (lane & 3) * 2;
        #pragma unroll
        for (int mi = 0; mi < 2; ++mi) {
            int r0 = er + mi * 16;
            int r1 = r0 + 8;
            float w0 = cw_s[r0], w1 = cw_s[r1];
            #pragma unroll
            for (int ni = 0; ni < 8; ++ni) {
                int col = ec0 + ni * 8;
                float x00 = c[mi][ni][0], x01 = c[mi][ni][1];
                float x10 = c[mi][ni][2], x11 = c[mi][ni][3];
                float v00 = x00 / (1.f + __expf(-x00)) * w0;
                float v01 = x01 / (1.f + __expf(-x01)) * w0;
                float v10 = x10 / (1.f + __expf(-x10)) * w1;
                float v11 = x11 / (1.f + __expf(-x11)) * w1;
                *(__half2*)(smc + S_OFF + r0 * ROW2_B + col * 2) =
                    __half2(__float2half(v00), __float2half(v01));
                *(__half2*)(smc + S_OFF + r1 * ROW2_B + col * 2) =
                    __half2(__float2half(v10), __float2half(v11));
            }
        }
    }
    __syncthreads();

    // ---------------- Phase 2: down-projection, 16 d-tiles (K = 128) --------
    const int vrow = tid >> 1;
    const int vc0  = (tid & 1) * 8;
    const __half* gv = g_vf + (size_t)e * DM * RR + (size_t)vrow * RR + vc0 * 8;

    auto issue_v = [&](int dt, int buf) {
        const uint32_t s0 = sbase + V_OFF + buf * 34816
                          + (uint32_t)(vrow * ROW2_B + vc0 * 16);
        const __half* g = gv + (size_t)dt * 128 * RR;
        #pragma unroll
        for (int i = 0; i < 8; ++i)
            CP_ASYNC16(s0 + i * 16, g + i * 8);
        CP_COMMIT();
    };

    issue_v(0, 0);
    for (int dt = 0; dt < 16; ++dt) {
        const int buf = dt & 1;
        if (dt + 1 < 16) { issue_v(dt + 1, buf ^ 1); CP_WAIT1(); }
        else             { CP_WAIT0(); }
        __syncthreads();

        const uint32_t vb = sbase + V_OFF + buf * 34816;
        float c[2][8][4];
        #pragma unroll
        for (int mi = 0; mi < 2; ++mi)
            #pragma unroll
            for (int ni = 0; ni < 8; ++ni)
                #pragma unroll
                for (int q = 0; q < 4; ++q) c[mi][ni][q] = 0.f;

        #pragma unroll
        for (int ks = 0; ks < 8; ++ks) {
            uint32_t af[2][4], bf[4][4];
            #pragma unroll
            for (int mi = 0; mi < 2; ++mi) {
                uint32_t ao = (uint32_t)((warp_m + mi * 16 + a_r) * ROW2_B
                                         + (ks * 16 + a_k) * 2);
                ldm_x4(af[mi], sbase + S_OFF + ao);
            }
            #pragma unroll
            for (int nb = 0; nb < 4; ++nb) {
                uint32_t bo = (uint32_t)((warp_n + nb * 16 + b_r) * ROW2_B
                                         + (ks * 16 + b_k) * 2);
                ldm_x4(bf[nb], vb + bo);
            }
            #pragma unroll
            for (int mi = 0; mi < 2; ++mi)
                #pragma unroll
                for (int nb = 0; nb < 4; ++nb) {
                    mma_f16(c[mi][nb*2],   af[mi], &bf[nb][0]);
                    mma_f16(c[mi][nb*2+1], af[mi], &bf[nb][2]);
                }
        }

        const int lr0 = warp_m + (lane >> 2);
        const int col0 = dt * 128 + warp_n + (lane & 3) * 2;
        #pragma unroll
        for (int mi = 0; mi < 2; ++mi) {
            int r0 = lr0 + mi * 16;
            int r1 = r0 + 8;
            #pragma unroll
            for (int ni = 0; ni < 8; ++ni) {
                int col = col0 + ni * 8;
                if (t0 + r0 < n) {
                    float* p = out + (size_t)tok_s[r0] * DM + col;
                    atomicAdd(p,     c[mi][ni][0]);
                    atomicAdd(p + 1, c[mi][ni][1]);
                }
                if (t0 + r1 < n) {
                    float* p = out + (size_t)tok_s[r1] * DM + col;
                    atomicAdd(p,     c[mi][ni][2]);
                    atomicAdd(p + 1, c[mi][ni][3]);
                }
            }
        }
        __syncthreads();
    }
}

extern "C" void kernel_launch(void* const* d_in, const int* in_sizes, int n_in,
                              void* d_out, int out_size)
{
    const float* x    = (const float*)d_in[0];
    const float* Wenc = (const float*)d_in[1];
    const float* benc = (const float*)d_in[2];
    const float* Wg   = (const float*)d_in[3];
    const float* U    = (const float*)d_in[4];
    const float* V    = (const float*)d_in[5];
    const float* gm   = (const float*)d_in[6];
    float* out = (float*)d_out;

    cudaFuncSetAttribute(encoder_mma,
                         cudaFuncAttributeMaxDynamicSharedMemorySize, ENC_SMEM);
    cudaFuncSetAttribute(expert_f16,
                         cudaFuncAttributeMaxDynamicSharedMemorySize, EXPF_SMEM);

    __half *xf, *wf, *uf, *vf;
    cudaGetSymbolAddress((void**)&xf, g_xf);
    cudaGetSymbolAddress((void**)&wf, g_wf);
    cudaGetSymbolAddress((void**)&uf, g_uf);
    cudaGetSymbolAddress((void**)&vf, g_vf);

    const int nx = B_TOK * DM, nw = DM * DM, nu = NEXP * RR * DM;
    cvt_f16<<<(nx/4 + 255)/256, 256>>>(x, xf, nx);
    cvt_f16<<<(nw/4 + 255)/256, 256>>>(Wenc, wf, nw);
    cvt_f16<<<(nu/4 + 255)/256, 256>>>(U, uf, nu);
    cvt_f16<<<(nu/4 + 255)/256, 256>>>(V, vf, nu);
    weff_kernel<<<DM/256, 256>>>(Wg, Wenc, benc);
    zero_counts<<<1, 32>>>();
    routing_kernel<<<B_TOK/16, 256>>>(x);
    encoder_mma<<<dim3(DM/128, B_TOK/128), 256, ENC_SMEM>>>(benc, out);
    expert_f16<<<dim3(B_TOK/128, NEXP), 256, EXPF_SMEM>>>(gm, out);
}